// round 3
// baseline (speedup 1.0000x reference)
#include <cuda_runtime.h>
#include <cuda_bf16.h>
#include <cstdint>

// ---------------------------------------------------------------------------
// ConditionedAttnGRUDecoder  (H=768, V=32000, TF=1024, B=4, T=512)
// Simplifications proven from the reference:
//  * softmax over length-1 axis == 1  -> ctx == h_prev, attentions == ones,
//    Wa/ba/Ua/ub/Va/vb are dead inputs.
//  * log_softmax twice == once.
//  * output projection doesn't feed the recurrence -> batch it as one GEMM.
// ---------------------------------------------------------------------------

#define HDIM 768
#define BDIM 4
#define TDIM 512
#define TFDIM 1024
#define VDIM 32000
#define MDIM (BDIM * TDIM)       // 2048

#define NCTA_A 96                // phase-A CTAs (768 warps = one per hidden j)

typedef unsigned long long ull;

// ----------------------------- device scratch ------------------------------
__device__ float g_Hall[(size_t)MDIM * HDIM];   // h_t for every (b*T+t)
__device__ float g_h[2][BDIM * HDIM];           // double-buffered hidden state
__device__ unsigned g_bar_count = 0;
__device__ unsigned g_bar_gen = 0;

// ----------------------------- helpers -------------------------------------
__device__ __forceinline__ ull fma2(ull a, ull b, ull c) {
    ull d;
    asm("fma.rn.f32x2 %0, %1, %2, %3;" : "=l"(d) : "l"(a), "l"(b), "l"(c));
    return d;
}
__device__ __forceinline__ ull pack2(float x, float y) {
    ull r;
    asm("mov.b64 %0, {%1, %2};" : "=l"(r) : "f"(x), "f"(y));
    return r;
}
__device__ __forceinline__ float2 unpack2(ull v) {
    float2 r;
    asm("mov.b64 {%0, %1}, %2;" : "=f"(r.x), "=f"(r.y) : "l"(v));
    return r;
}
__device__ __forceinline__ float wredsum(float v) {
#pragma unroll
    for (int o = 16; o; o >>= 1) v += __shfl_xor_sync(0xffffffffu, v, o);
    return v;
}
__device__ __forceinline__ float wredmax(float v) {
#pragma unroll
    for (int o = 16; o; o >>= 1) v = fmaxf(v, __shfl_xor_sync(0xffffffffu, v, o));
    return v;
}
__device__ __forceinline__ float sigmoidf_(float x) {
    return 1.0f / (1.0f + __expf(-x));
}

// grid-wide barrier (all NCTA_A CTAs resident: grid 96 <= 148 SMs, occ 1)
__device__ __forceinline__ void grid_barrier() {
    __syncthreads();
    if (threadIdx.x == 0) {
        __threadfence();
        unsigned gen = *(volatile unsigned*)&g_bar_gen;
        unsigned t = atomicAdd(&g_bar_count, 1u);
        if (t == NCTA_A - 1) {
            g_bar_count = 0;
            __threadfence();
            atomicExch(&g_bar_gen, gen + 1u);
        } else {
            while (*(volatile unsigned*)&g_bar_gen == gen) { __nanosleep(64); }
        }
        __threadfence();
    }
    __syncthreads();
}

// ---------------------------------------------------------------------------
// Phase A: h0 (tfidf gather @ lyr_W.T) + 512 sequential GRU steps.
// One warp owns one hidden index j (96 CTAs x 8 warps = 768).
// Weights streamed from global (L2-resident, 3.5 MB). Packed f32x2 FMA.
// ---------------------------------------------------------------------------
__global__ void __launch_bounds__(256, 1)
gru_kernel(const int* __restrict__ lyr, const int* __restrict__ iseq,
           const int* __restrict__ tgt, const float* __restrict__ emb,
           const float* __restrict__ tfidf_, const float* __restrict__ lyrW,
           const float* __restrict__ lyrb, const float* __restrict__ Wih,
           const float* __restrict__ Whh, const float* __restrict__ bih,
           const float* __restrict__ bhh) {
    __shared__ float sx[BDIM * HDIM];
    __shared__ float sh[BDIM * HDIM];

    const int tid = threadIdx.x;
    const int lane = tid & 31;
    const int wid = tid >> 5;
    const int j = blockIdx.x * 8 + wid;   // hidden index owned by this warp

    // hoisted biases for this j
    const float bir = bih[j],            bhr = bhh[j];
    const float biz = bih[HDIM + j],     bhz = bhh[HDIM + j];
    const float bin = bih[2 * HDIM + j], bhn = bhh[2 * HDIM + j];

    // ---- h0[b][j] = dot(tfidf[lyr[b]], lyr_W[j]) + lyr_b[j] ----
    {
        const float* wrow = lyrW + (size_t)j * TFDIM;
#pragma unroll
        for (int b = 0; b < BDIM; ++b) {
            const float* trow = tfidf_ + (size_t)lyr[b] * TFDIM;
            float acc = 0.0f;
#pragma unroll
            for (int it = 0; it < 8; ++it) {
                int k = it * 128 + lane * 4;
                float4 tv = *(const float4*)(trow + k);
                float4 wv = *(const float4*)(wrow + k);
                acc = fmaf(tv.x, wv.x, acc);
                acc = fmaf(tv.y, wv.y, acc);
                acc = fmaf(tv.z, wv.z, acc);
                acc = fmaf(tv.w, wv.w, acc);
            }
            acc = wredsum(acc);
            if (lane == 0) g_h[0][b * HDIM + j] = acc + lyrb[j];
        }
    }
    grid_barrier();

    const float* wiR = Wih + (size_t)(0 * HDIM + j) * HDIM;
    const float* wiZ = Wih + (size_t)(1 * HDIM + j) * HDIM;
    const float* wiN = Wih + (size_t)(2 * HDIM + j) * HDIM;
    const float* whR = Whh + (size_t)(0 * HDIM + j) * HDIM;
    const float* whZ = Whh + (size_t)(1 * HDIM + j) * HDIM;
    const float* whN = Whh + (size_t)(2 * HDIM + j) * HDIM;

    for (int t = 0; t < TDIM; ++t) {
        const int rb = t & 1, wb = rb ^ 1;

        // stage x_t and h_{t-1} into shared
#pragma unroll
        for (int b = 0; b < BDIM; ++b) {
            int tok = (t == 0) ? iseq[b * TDIM] : tgt[b * TDIM + t - 1];
            const float* xr = emb + (size_t)tok * HDIM;
            for (int k = tid; k < HDIM; k += 256) {
                sx[b * HDIM + k] = xr[k];
                sh[b * HDIM + k] = g_h[rb][b * HDIM + k];
            }
        }
        __syncthreads();

        ull ai[3][BDIM], ah[3][BDIM];
#pragma unroll
        for (int g = 0; g < 3; ++g)
#pragma unroll
            for (int b = 0; b < BDIM; ++b) { ai[g][b] = 0ULL; ah[g][b] = 0ULL; }

        const float* wi[3] = {wiR, wiZ, wiN};
        const float* wh[3] = {whR, whZ, whN};

#pragma unroll
        for (int g = 0; g < 3; ++g) {
#pragma unroll
            for (int it = 0; it < 6; ++it) {
                const int k = it * 128 + lane * 4;
                ulonglong2 wiv = *(const ulonglong2*)(wi[g] + k);
                ulonglong2 whv = *(const ulonglong2*)(wh[g] + k);
#pragma unroll
                for (int b = 0; b < BDIM; ++b) {
                    const float* xb = sx + b * HDIM + k;
                    const float* hb = sh + b * HDIM + k;
                    ull x01 = *(const ull*)(xb);
                    ull x23 = *(const ull*)(xb + 2);
                    ull h01 = *(const ull*)(hb);
                    ull h23 = *(const ull*)(hb + 2);
                    ai[g][b] = fma2(wiv.x, x01, ai[g][b]);
                    ai[g][b] = fma2(wiv.y, x23, ai[g][b]);
                    ah[g][b] = fma2(whv.x, h01, ah[g][b]);
                    ah[g][b] = fma2(whv.y, h23, ah[g][b]);
                }
            }
        }

        // reduce 24 dots across the warp
        float gi[3][BDIM], gh[3][BDIM];
#pragma unroll
        for (int g = 0; g < 3; ++g)
#pragma unroll
            for (int b = 0; b < BDIM; ++b) {
                float2 v = unpack2(ai[g][b]);
                gi[g][b] = wredsum(v.x + v.y);
                float2 w = unpack2(ah[g][b]);
                gh[g][b] = wredsum(w.x + w.y);
            }

        if (lane == 0) {
#pragma unroll
            for (int b = 0; b < BDIM; ++b) {
                float r = sigmoidf_(gi[0][b] + bir + gh[0][b] + bhr);
                float z = sigmoidf_(gi[1][b] + biz + gh[1][b] + bhz);
                float n = tanhf(gi[2][b] + bin + r * (gh[2][b] + bhn));
                float hp = sh[b * HDIM + j];
                float hn = (1.0f - z) * n + z * hp;
                g_h[wb][b * HDIM + j] = hn;
                g_Hall[((size_t)b * TDIM + t) * HDIM + j] = hn;
            }
        }
        grid_barrier();
    }
}

// ---------------------------------------------------------------------------
// Phase B: C[2048, 32000] = g_Hall @ out_W.T + out_b  (fp32, f32x2 FFMA)
// Tile 64(M) x 128(N) x 32(K), 256 threads, thread micro-tile 4x8.
// Grid x = m-tiles (fast) so concurrently-running CTAs share W tiles in L2.
// ---------------------------------------------------------------------------
#define MT 64
#define NT 128
#define KC 32

__global__ void __launch_bounds__(256)
gemm_kernel(const float* __restrict__ outW, const float* __restrict__ outb,
            float* __restrict__ out) {
    __shared__ float sA[KC][MT];   // 8 KB
    __shared__ float sW[KC][NT];   // 16 KB

    const int tid = threadIdx.x;
    const int m0g = blockIdx.x * MT;
    const int n0g = blockIdx.y * NT;
    const int tm = tid & 15;       // m micro: 4 rows at tm*4
    const int tn = tid >> 4;       // n micro: 8 cols at tn*8

    ull c2[4][4];
#pragma unroll
    for (int i = 0; i < 4; ++i)
#pragma unroll
        for (int jj = 0; jj < 4; ++jj) c2[i][jj] = 0ULL;

    for (int kc = 0; kc < HDIM / KC; ++kc) {
        const int kbase = kc * KC;
        // load A tile: 64x32
#pragma unroll
        for (int q = 0; q < 2; ++q) {
            int idx = q * 256 + tid;
            int m = idx & 63;
            int k4 = (idx >> 6) * 4;
            float4 a = *(const float4*)(g_Hall + (size_t)(m0g + m) * HDIM + kbase + k4);
            sA[k4 + 0][m] = a.x; sA[k4 + 1][m] = a.y;
            sA[k4 + 2][m] = a.z; sA[k4 + 3][m] = a.w;
        }
        // load W tile: 128x32
#pragma unroll
        for (int q = 0; q < 4; ++q) {
            int idx = q * 256 + tid;
            int n = idx & 127;
            int k4 = (idx >> 7) * 4;
            float4 w = *(const float4*)(outW + (size_t)(n0g + n) * HDIM + kbase + k4);
            sW[k4 + 0][n] = w.x; sW[k4 + 1][n] = w.y;
            sW[k4 + 2][n] = w.z; sW[k4 + 3][n] = w.w;
        }
        __syncthreads();

#pragma unroll 8
        for (int kk = 0; kk < KC; ++kk) {
            float4 a4 = *(const float4*)(&sA[kk][tm * 4]);
            ulonglong2 wA = *(const ulonglong2*)(&sW[kk][tn * 8]);
            ulonglong2 wB = *(const ulonglong2*)(&sW[kk][tn * 8 + 4]);
            ull a2[4];
            a2[0] = pack2(a4.x, a4.x);
            a2[1] = pack2(a4.y, a4.y);
            a2[2] = pack2(a4.z, a4.z);
            a2[3] = pack2(a4.w, a4.w);
#pragma unroll
            for (int i = 0; i < 4; ++i) {
                c2[i][0] = fma2(a2[i], wA.x, c2[i][0]);
                c2[i][1] = fma2(a2[i], wA.y, c2[i][1]);
                c2[i][2] = fma2(a2[i], wB.x, c2[i][2]);
                c2[i][3] = fma2(a2[i], wB.y, c2[i][3]);
            }
        }
        __syncthreads();
    }

    // epilogue: add bias, store
#pragma unroll
    for (int i = 0; i < 4; ++i) {
        const int row = m0g + tm * 4 + i;
        float* orow = out + (size_t)row * VDIM + n0g + tn * 8;
#pragma unroll
        for (int jj = 0; jj < 4; ++jj) {
            float2 v = unpack2(c2[i][jj]);
            int col = n0g + tn * 8 + jj * 2;
            v.x += outb[col];
            v.y += outb[col + 1];
            *(float2*)(orow + jj * 2) = v;
        }
    }
}

// ---------------------------------------------------------------------------
// Row-wise log_softmax in-place over V=32000 (one CTA per row).
// ---------------------------------------------------------------------------
__global__ void __launch_bounds__(256)
logsoftmax_kernel(float* __restrict__ out) {
    __shared__ float red[8];
    const int tid = threadIdx.x;
    const int lane = tid & 31;
    const int wid = tid >> 5;
    float* x = out + (size_t)blockIdx.x * VDIM;

    float m = -3.4e38f;
    for (int i = tid; i < VDIM; i += 256) m = fmaxf(m, x[i]);
    m = wredmax(m);
    if (lane == 0) red[wid] = m;
    __syncthreads();
    m = red[0];
#pragma unroll
    for (int w = 1; w < 8; ++w) m = fmaxf(m, red[w]);
    __syncthreads();

    float s = 0.0f;
    for (int i = tid; i < VDIM; i += 256) s += __expf(x[i] - m);
    s = wredsum(s);
    if (lane == 0) red[wid] = s;
    __syncthreads();
    s = red[0];
#pragma unroll
    for (int w = 1; w < 8; ++w) s += red[w];

    const float lse = m + logf(s);
    for (int i = tid; i < VDIM; i += 256) x[i] -= lse;
}

// ---------------------------------------------------------------------------
// Tail: h_last (= g_h buffer 0 after 512 steps) and attentions (= ones).
// ---------------------------------------------------------------------------
__global__ void tail_kernel(float* __restrict__ out) {
    const int i = blockIdx.x * 256 + threadIdx.x;
    const size_t HOFF = (size_t)MDIM * VDIM;            // 65,536,000
    if (i < BDIM * HDIM) out[HOFF + i] = g_h[0][i];
    if (i < BDIM * TDIM) out[HOFF + BDIM * HDIM + i] = 1.0f;
}

// ---------------------------------------------------------------------------
extern "C" void kernel_launch(void* const* d_in, const int* in_sizes, int n_in,
                              void* d_out, int out_size) {
    const int*   lyr   = (const int*)d_in[0];
    const int*   iseq  = (const int*)d_in[1];
    const int*   tgt   = (const int*)d_in[2];
    const float* emb   = (const float*)d_in[3];
    // d_in[4..9]: Wa, ba, Ua, ub, Va, vb  -> provably dead (softmax over len-1)
    const float* tfidf_ = (const float*)d_in[10];
    const float* lyrW  = (const float*)d_in[11];
    const float* lyrb  = (const float*)d_in[12];
    const float* Wih   = (const float*)d_in[13];
    const float* Whh   = (const float*)d_in[14];
    const float* bih   = (const float*)d_in[15];
    const float* bhh   = (const float*)d_in[16];
    const float* outW  = (const float*)d_in[17];
    const float* outb  = (const float*)d_in[18];
    float* out = (float*)d_out;

    gru_kernel<<<NCTA_A, 256>>>(lyr, iseq, tgt, emb, tfidf_, lyrW, lyrb,
                                Wih, Whh, bih, bhh);

    dim3 gg(MDIM / MT, VDIM / NT);   // (32, 250), x fastest -> W tiles L2-hot
    gemm_kernel<<<gg, 256>>>(outW, outb, out);

    logsoftmax_kernel<<<MDIM, 256>>>(out);

    tail_kernel<<<(BDIM * TDIM + 255) / 256 + 12, 256>>>(out);
}

// round 5
// speedup vs baseline: 1.4262x; 1.4262x over previous
#include <cuda_runtime.h>
#include <cuda_bf16.h>
#include <cstdint>

// ---------------------------------------------------------------------------
// ConditionedAttnGRUDecoder  (H=768, V=32000, TF=1024, B=4, T=512)
//  * softmax over length-1 axis == 1 -> ctx == h_prev, attentions == ones,
//    Wa/ba/Ua/ub/Va/vb are dead inputs.
//  * log_softmax twice == once.
//  * output projection batched as ONE bf16 HMMA GEMM (mma.sync m16n8k16).
//    NOTE: harness compiles for plain sm_103 -> tcgen05/a-features unusable.
// ---------------------------------------------------------------------------

#define HDIM 768
#define BDIM 4
#define TDIM 512
#define TFDIM 1024
#define VDIM 32000
#define MDIM (BDIM * TDIM)       // 2048

#define NCTA_A 96                // phase-A CTAs (768 warps = one per hidden j)

typedef unsigned long long ull;

// ----------------------------- device scratch ------------------------------
__device__ float g_Hall[(size_t)MDIM * HDIM];           // h_t for every (b*T+t)
__device__ float g_h[2][BDIM * HDIM];                   // hidden double buffer
__device__ __align__(16) __nv_bfloat16 g_Hbf[(size_t)MDIM * HDIM];
__device__ __align__(16) __nv_bfloat16 g_Wbf[(size_t)VDIM * HDIM];
__device__ unsigned g_bar_count = 0;
__device__ unsigned g_bar_gen = 0;

// ----------------------------- scalar helpers ------------------------------
__device__ __forceinline__ ull fma2(ull a, ull b, ull c) {
    ull d;
    asm("fma.rn.f32x2 %0, %1, %2, %3;" : "=l"(d) : "l"(a), "l"(b), "l"(c));
    return d;
}
__device__ __forceinline__ float2 unpack2(ull v) {
    float2 r;
    asm("mov.b64 {%0, %1}, %2;" : "=f"(r.x), "=f"(r.y) : "l"(v));
    return r;
}
__device__ __forceinline__ float wredsum(float v) {
#pragma unroll
    for (int o = 16; o; o >>= 1) v += __shfl_xor_sync(0xffffffffu, v, o);
    return v;
}
__device__ __forceinline__ float wredmax(float v) {
#pragma unroll
    for (int o = 16; o; o >>= 1) v = fmaxf(v, __shfl_xor_sync(0xffffffffu, v, o));
    return v;
}
__device__ __forceinline__ float sigmoidf_(float x) {
    return 1.0f / (1.0f + __expf(-x));
}
__device__ __forceinline__ uint32_t smem_u32(const void* p) {
    uint32_t a;
    asm("{ .reg .u64 t; cvta.to.shared.u64 t, %1; cvt.u32.u64 %0, t; }"
        : "=r"(a) : "l"(p));
    return a;
}

// grid-wide barrier (all NCTA_A CTAs resident)
__device__ __forceinline__ void grid_barrier() {
    __syncthreads();
    if (threadIdx.x == 0) {
        __threadfence();
        unsigned gen = *(volatile unsigned*)&g_bar_gen;
        unsigned t = atomicAdd(&g_bar_count, 1u);
        if (t == NCTA_A - 1) {
            g_bar_count = 0;
            __threadfence();
            atomicExch(&g_bar_gen, gen + 1u);
        } else {
            while (*(volatile unsigned*)&g_bar_gen == gen) { __nanosleep(64); }
        }
        __threadfence();
    }
    __syncthreads();
}

// ---------------------------------------------------------------------------
// Phase A: h0 + 512 sequential GRU steps (fp32) — unchanged from R3 pass.
// ---------------------------------------------------------------------------
__global__ void __launch_bounds__(256, 1)
gru_kernel(const int* __restrict__ lyr, const int* __restrict__ iseq,
           const int* __restrict__ tgt, const float* __restrict__ emb,
           const float* __restrict__ tfidf_, const float* __restrict__ lyrW,
           const float* __restrict__ lyrb, const float* __restrict__ Wih,
           const float* __restrict__ Whh, const float* __restrict__ bih,
           const float* __restrict__ bhh) {
    __shared__ float sx[BDIM * HDIM];
    __shared__ float sh[BDIM * HDIM];

    const int tid = threadIdx.x;
    const int lane = tid & 31;
    const int wid = tid >> 5;
    const int j = blockIdx.x * 8 + wid;

    const float bir = bih[j],            bhr = bhh[j];
    const float biz = bih[HDIM + j],     bhz = bhh[HDIM + j];
    const float bin = bih[2 * HDIM + j], bhn = bhh[2 * HDIM + j];

    {
        const float* wrow = lyrW + (size_t)j * TFDIM;
#pragma unroll
        for (int b = 0; b < BDIM; ++b) {
            const float* trow = tfidf_ + (size_t)lyr[b] * TFDIM;
            float acc = 0.0f;
#pragma unroll
            for (int it = 0; it < 8; ++it) {
                int k = it * 128 + lane * 4;
                float4 tv = *(const float4*)(trow + k);
                float4 wv = *(const float4*)(wrow + k);
                acc = fmaf(tv.x, wv.x, acc);
                acc = fmaf(tv.y, wv.y, acc);
                acc = fmaf(tv.z, wv.z, acc);
                acc = fmaf(tv.w, wv.w, acc);
            }
            acc = wredsum(acc);
            if (lane == 0) g_h[0][b * HDIM + j] = acc + lyrb[j];
        }
    }
    grid_barrier();

    const float* wi[3] = {Wih + (size_t)j * HDIM,
                          Wih + (size_t)(HDIM + j) * HDIM,
                          Wih + (size_t)(2 * HDIM + j) * HDIM};
    const float* wh[3] = {Whh + (size_t)j * HDIM,
                          Whh + (size_t)(HDIM + j) * HDIM,
                          Whh + (size_t)(2 * HDIM + j) * HDIM};

    for (int t = 0; t < TDIM; ++t) {
        const int rb = t & 1, wb = rb ^ 1;
#pragma unroll
        for (int b = 0; b < BDIM; ++b) {
            int tok = (t == 0) ? iseq[b * TDIM] : tgt[b * TDIM + t - 1];
            const float* xr = emb + (size_t)tok * HDIM;
            for (int k = tid; k < HDIM; k += 256) {
                sx[b * HDIM + k] = xr[k];
                sh[b * HDIM + k] = g_h[rb][b * HDIM + k];
            }
        }
        __syncthreads();

        ull ai[3][BDIM], ah[3][BDIM];
#pragma unroll
        for (int g = 0; g < 3; ++g)
#pragma unroll
            for (int b = 0; b < BDIM; ++b) { ai[g][b] = 0ULL; ah[g][b] = 0ULL; }

#pragma unroll
        for (int g = 0; g < 3; ++g) {
#pragma unroll
            for (int it = 0; it < 6; ++it) {
                const int k = it * 128 + lane * 4;
                ulonglong2 wiv = *(const ulonglong2*)(wi[g] + k);
                ulonglong2 whv = *(const ulonglong2*)(wh[g] + k);
#pragma unroll
                for (int b = 0; b < BDIM; ++b) {
                    const float* xb = sx + b * HDIM + k;
                    const float* hb = sh + b * HDIM + k;
                    ull x01 = *(const ull*)(xb);
                    ull x23 = *(const ull*)(xb + 2);
                    ull h01 = *(const ull*)(hb);
                    ull h23 = *(const ull*)(hb + 2);
                    ai[g][b] = fma2(wiv.x, x01, ai[g][b]);
                    ai[g][b] = fma2(wiv.y, x23, ai[g][b]);
                    ah[g][b] = fma2(whv.x, h01, ah[g][b]);
                    ah[g][b] = fma2(whv.y, h23, ah[g][b]);
                }
            }
        }

        float gi[3][BDIM], gh[3][BDIM];
#pragma unroll
        for (int g = 0; g < 3; ++g)
#pragma unroll
            for (int b = 0; b < BDIM; ++b) {
                float2 v = unpack2(ai[g][b]);
                gi[g][b] = wredsum(v.x + v.y);
                float2 w = unpack2(ah[g][b]);
                gh[g][b] = wredsum(w.x + w.y);
            }

        if (lane == 0) {
#pragma unroll
            for (int b = 0; b < BDIM; ++b) {
                float r = sigmoidf_(gi[0][b] + bir + gh[0][b] + bhr);
                float z = sigmoidf_(gi[1][b] + biz + gh[1][b] + bhz);
                float n = tanhf(gi[2][b] + bin + r * (gh[2][b] + bhn));
                float hp = sh[b * HDIM + j];
                float hn = (1.0f - z) * n + z * hp;
                g_h[wb][b * HDIM + j] = hn;
                g_Hall[((size_t)b * TDIM + t) * HDIM + j] = hn;
            }
        }
        grid_barrier();
    }
}

// ---------------------------------------------------------------------------
// fp32 -> bf16 convert: out_W and g_Hall (after GRU).
// ---------------------------------------------------------------------------
__global__ void __launch_bounds__(256)
convert_kernel(const float* __restrict__ outW) {
    const size_t i0 = (size_t)blockIdx.x * blockDim.x + threadIdx.x;
    const size_t stride = (size_t)gridDim.x * blockDim.x;
    const size_t NW4 = (size_t)VDIM * HDIM / 4;
    const size_t NH4 = (size_t)MDIM * HDIM / 4;
    for (size_t k = i0; k < NW4; k += stride) {
        float4 v = ((const float4*)outW)[k];
        ((__nv_bfloat162*)g_Wbf)[k * 2]     = __floats2bfloat162_rn(v.x, v.y);
        ((__nv_bfloat162*)g_Wbf)[k * 2 + 1] = __floats2bfloat162_rn(v.z, v.w);
    }
    for (size_t k = i0; k < NH4; k += stride) {
        float4 v = ((const float4*)g_Hall)[k];
        ((__nv_bfloat162*)g_Hbf)[k * 2]     = __floats2bfloat162_rn(v.x, v.y);
        ((__nv_bfloat162*)g_Hbf)[k * 2 + 1] = __floats2bfloat162_rn(v.z, v.w);
    }
}

// ---------------------------------------------------------------------------
// Phase B: HMMA GEMM  C[2048,32000] = Hbf @ Wbf.T + out_b
// mma.sync.m16n8k16 bf16 (portable, no 'a' features).
// CTA tile 128x128, k-chunk 32, 8 warps (4M x 2N), warp tile 32x64.
// Smem rows padded to 40 bf16 (80B) -> conflict-free ldmatrix.
// ---------------------------------------------------------------------------
#define TM 128
#define TN 128
#define TK 32
#define NCHUNK (HDIM / TK)       // 24
#define SPAD 40                  // bf16 per smem row (80B stride)

__device__ __forceinline__ void ldmx4(uint32_t* r, uint32_t addr) {
    asm volatile("ldmatrix.sync.aligned.m8n8.x4.shared.b16 {%0,%1,%2,%3}, [%4];"
                 : "=r"(r[0]), "=r"(r[1]), "=r"(r[2]), "=r"(r[3]) : "r"(addr));
}
__device__ __forceinline__ void hmma(float* d, const uint32_t* a,
                                     const uint32_t* b) {
    asm volatile(
        "mma.sync.aligned.m16n8k16.row.col.f32.bf16.bf16.f32 "
        "{%0,%1,%2,%3}, {%4,%5,%6,%7}, {%8,%9}, {%0,%1,%2,%3};"
        : "+f"(d[0]), "+f"(d[1]), "+f"(d[2]), "+f"(d[3])
        : "r"(a[0]), "r"(a[1]), "r"(a[2]), "r"(a[3]), "r"(b[0]), "r"(b[1]));
}

__global__ void __launch_bounds__(256, 2)
gemm_kernel(const float* __restrict__ outb, float* __restrict__ out) {
    __shared__ __nv_bfloat16 sA[2][TM][SPAD];
    __shared__ __nv_bfloat16 sB[2][TN][SPAD];
    __shared__ float sbias[TN];

    const int tid = threadIdx.x;
    const int lane = tid & 31;
    const int wid = tid >> 5;
    const int wm = wid & 3;         // 4 m-warps (32 rows each)
    const int wn = wid >> 2;        // 2 n-warps (64 cols each)
    const size_t m0 = (size_t)blockIdx.x * TM;
    const size_t n0 = (size_t)blockIdx.y * TN;

    for (int i = tid; i < TN; i += 256) sbias[i] = outb[n0 + i];

    // per-thread global<->smem mapping: 512 uint4 per tile, 2 per thread
    const int grow = tid >> 2;            // 0..63 (x2 via q)
    const int gseg = tid & 3;             // 16B segment within 64B row-chunk

    const __nv_bfloat16* gA = g_Hbf + (m0 + grow) * HDIM + gseg * 8;
    const __nv_bfloat16* gB = g_Wbf + (n0 + grow) * HDIM + gseg * 8;

    // initial chunk 0 -> buffer 0
    {
#pragma unroll
        for (int q = 0; q < 2; ++q) {
            uint4 a = *(const uint4*)(gA + q * 64 * HDIM);
            uint4 b = *(const uint4*)(gB + q * 64 * HDIM);
            *(uint4*)(&sA[0][grow + q * 64][gseg * 8]) = a;
            *(uint4*)(&sB[0][grow + q * 64][gseg * 8]) = b;
        }
    }
    __syncthreads();

    float acc[2][8][4];
#pragma unroll
    for (int am = 0; am < 2; ++am)
#pragma unroll
        for (int bn = 0; bn < 8; ++bn)
#pragma unroll
            for (int q = 0; q < 4; ++q) acc[am][bn][q] = 0.0f;

    // ldmatrix source addresses (within-buffer offsets recomputed per use)
    const int a_r = lane & 15, a_c = (lane >> 4) * 8;        // A x4 pattern
    const int b_g = lane >> 3;
    const int b_r = ((b_g >> 1) << 3) + (lane & 7);
    const int b_c = (b_g & 1) * 8;                            // B x4 pattern

    for (int c = 0; c < NCHUNK; ++c) {
        const int p = c & 1;
        const bool more = (c + 1) < NCHUNK;
        uint4 pa0, pa1, pb0, pb1;
        if (more) {
            const __nv_bfloat16* sa = gA + (size_t)(c + 1) * TK;
            const __nv_bfloat16* sb2 = gB + (size_t)(c + 1) * TK;
            pa0 = *(const uint4*)(sa);
            pa1 = *(const uint4*)(sa + 64 * HDIM);
            pb0 = *(const uint4*)(sb2);
            pb1 = *(const uint4*)(sb2 + 64 * HDIM);
        }

#pragma unroll
        for (int ks = 0; ks < 2; ++ks) {
            const int k8 = ks * 16;
            uint32_t afr[2][4], bfr[4][4];
#pragma unroll
            for (int am = 0; am < 2; ++am)
                ldmx4(afr[am],
                      smem_u32(&sA[p][wm * 32 + am * 16 + a_r][k8 + a_c]));
#pragma unroll
            for (int bg = 0; bg < 4; ++bg)
                ldmx4(bfr[bg],
                      smem_u32(&sB[p][wn * 64 + bg * 16 + b_r][k8 + b_c]));
#pragma unroll
            for (int am = 0; am < 2; ++am)
#pragma unroll
                for (int bn = 0; bn < 8; ++bn)
                    hmma(acc[am][bn], afr[am], &bfr[bn >> 1][(bn & 1) * 2]);
        }

        if (more) {
            *(uint4*)(&sA[p ^ 1][grow][gseg * 8]) = pa0;
            *(uint4*)(&sA[p ^ 1][grow + 64][gseg * 8]) = pa1;
            *(uint4*)(&sB[p ^ 1][grow][gseg * 8]) = pb0;
            *(uint4*)(&sB[p ^ 1][grow + 64][gseg * 8]) = pb1;
        }
        __syncthreads();
    }

    // epilogue: add bias, store float2 per (atom, half)
#pragma unroll
    for (int am = 0; am < 2; ++am) {
#pragma unroll
        for (int half = 0; half < 2; ++half) {
            const size_t row = m0 + wm * 32 + am * 16 + half * 8 + (lane >> 2);
            float* orow = out + row * VDIM + n0 + wn * 64 + (lane & 3) * 2;
#pragma unroll
            for (int bn = 0; bn < 8; ++bn) {
                const int colL = wn * 64 + bn * 8 + (lane & 3) * 2;
                float2 v;
                v.x = acc[am][bn][half * 2 + 0] + sbias[colL];
                v.y = acc[am][bn][half * 2 + 1] + sbias[colL + 1];
                *(float2*)(orow + bn * 8) = v;
            }
        }
    }
}

// ---------------------------------------------------------------------------
// Row-wise log_softmax in-place over V=32000 (one CTA per row).
// ---------------------------------------------------------------------------
__global__ void __launch_bounds__(256)
logsoftmax_kernel(float* __restrict__ out) {
    __shared__ float red[8];
    const int tid = threadIdx.x;
    const int lane = tid & 31;
    const int wid = tid >> 5;
    float* x = out + (size_t)blockIdx.x * VDIM;

    float m = -3.4e38f;
    for (int i = tid; i < VDIM; i += 256) m = fmaxf(m, x[i]);
    m = wredmax(m);
    if (lane == 0) red[wid] = m;
    __syncthreads();
    m = red[0];
#pragma unroll
    for (int w = 1; w < 8; ++w) m = fmaxf(m, red[w]);
    __syncthreads();

    float s = 0.0f;
    for (int i = tid; i < VDIM; i += 256) s += __expf(x[i] - m);
    s = wredsum(s);
    if (lane == 0) red[wid] = s;
    __syncthreads();
    s = red[0];
#pragma unroll
    for (int w = 1; w < 8; ++w) s += red[w];

    const float lse = m + logf(s);
    for (int i = tid; i < VDIM; i += 256) x[i] -= lse;
}

// ---------------------------------------------------------------------------
// Tail: h_last and attentions (= ones).
// ---------------------------------------------------------------------------
__global__ void tail_kernel(float* __restrict__ out) {
    const int i = blockIdx.x * 256 + threadIdx.x;
    const size_t HOFF = (size_t)MDIM * VDIM;
    if (i < BDIM * HDIM) out[HOFF + i] = g_h[0][i];
    if (i < BDIM * TDIM) out[HOFF + BDIM * HDIM + i] = 1.0f;
}

// ---------------------------------------------------------------------------
extern "C" void kernel_launch(void* const* d_in, const int* in_sizes, int n_in,
                              void* d_out, int out_size) {
    const int*   lyr   = (const int*)d_in[0];
    const int*   iseq  = (const int*)d_in[1];
    const int*   tgt   = (const int*)d_in[2];
    const float* emb   = (const float*)d_in[3];
    // d_in[4..9]: Wa, ba, Ua, ub, Va, vb -> dead (softmax over length-1 axis)
    const float* tfidf_ = (const float*)d_in[10];
    const float* lyrW  = (const float*)d_in[11];
    const float* lyrb  = (const float*)d_in[12];
    const float* Wih   = (const float*)d_in[13];
    const float* Whh   = (const float*)d_in[14];
    const float* bih   = (const float*)d_in[15];
    const float* bhh   = (const float*)d_in[16];
    const float* outW  = (const float*)d_in[17];
    const float* outb  = (const float*)d_in[18];
    float* out = (float*)d_out;

    gru_kernel<<<NCTA_A, 256>>>(lyr, iseq, tgt, emb, tfidf_, lyrW, lyrb,
                                Wih, Whh, bih, bhh);

    convert_kernel<<<1024, 256>>>(outW);

    dim3 gg(MDIM / TM, VDIM / TN);   // (16, 250), x fastest -> W tiles L2-hot
    gemm_kernel<<<gg, 256>>>(outb, out);

    logsoftmax_kernel<<<MDIM, 256>>>(out);

    tail_kernel<<<(BDIM * TDIM + 255) / 256 + 12, 256>>>(out);
}

// round 6
// speedup vs baseline: 2.8914x; 2.0274x over previous
#include <cuda_runtime.h>
#include <cuda_bf16.h>
#include <cstdint>

// ---------------------------------------------------------------------------
// ConditionedAttnGRUDecoder  (H=768, V=32000, TF=1024, B=4, T=512)
//  * softmax over length-1 axis == 1 -> ctx == h_prev, attentions == ones,
//    Wa/ba/Ua/ub/Va/vb are dead inputs.
//  * log_softmax twice == once.
//  * gi = x@Wih^T precomputed for ALL steps (tokens known upfront).
//  * recurrent loop: only gh = h@Whh^T, with Whh in REGISTERS.
//  * output projection: ONE bf16 HMMA GEMM (portable mma.sync m16n8k16).
// ---------------------------------------------------------------------------

#define HDIM 768
#define BDIM 4
#define TDIM 512
#define TFDIM 1024
#define VDIM 32000
#define MDIM (BDIM * TDIM)       // 2048
#define GDIM (3 * HDIM)          // 2304

#define NCTA_A 96                // GRU CTAs (96 x 16 warps; 2 warps per j)

typedef unsigned long long ull;

// ----------------------------- device scratch ------------------------------
__device__ float g_h[2][BDIM * HDIM];                   // hidden double buffer
__device__ __align__(16) __nv_bfloat16 g_Hbf[(size_t)MDIM * HDIM];
__device__ __align__(16) __nv_bfloat16 g_Wbf[(size_t)VDIM * HDIM];
__device__ __align__(16) float g_gi[(size_t)MDIM * GDIM];   // precomputed x-gates
__device__ int g_stok[MDIM];                            // token per (t*4+b)
__device__ unsigned g_bar_count = 0;
__device__ unsigned g_bar_gen = 0;

// ----------------------------- helpers -------------------------------------
__device__ __forceinline__ ull fma2(ull a, ull b, ull c) {
    ull d;
    asm("fma.rn.f32x2 %0, %1, %2, %3;" : "=l"(d) : "l"(a), "l"(b), "l"(c));
    return d;
}
__device__ __forceinline__ ull pack2(float x, float y) {
    ull r;
    asm("mov.b64 %0, {%1, %2};" : "=l"(r) : "f"(x), "f"(y));
    return r;
}
__device__ __forceinline__ float2 unpack2(ull v) {
    float2 r;
    asm("mov.b64 {%0, %1}, %2;" : "=f"(r.x), "=f"(r.y) : "l"(v));
    return r;
}
__device__ __forceinline__ float wredsum(float v) {
#pragma unroll
    for (int o = 16; o; o >>= 1) v += __shfl_xor_sync(0xffffffffu, v, o);
    return v;
}
__device__ __forceinline__ float wredmax(float v) {
#pragma unroll
    for (int o = 16; o; o >>= 1) v = fmaxf(v, __shfl_xor_sync(0xffffffffu, v, o));
    return v;
}
__device__ __forceinline__ float sigmoidf_(float x) {
    return 1.0f / (1.0f + __expf(-x));
}
__device__ __forceinline__ uint32_t smem_u32(const void* p) {
    uint32_t a;
    asm("{ .reg .u64 t; cvta.to.shared.u64 t, %1; cvt.u32.u64 %0, t; }"
        : "=r"(a) : "l"(p));
    return a;
}

// grid-wide barrier (all NCTA_A CTAs resident)
__device__ __forceinline__ void grid_barrier() {
    __syncthreads();
    if (threadIdx.x == 0) {
        __threadfence();
        unsigned gen = *(volatile unsigned*)&g_bar_gen;
        unsigned t = atomicAdd(&g_bar_count, 1u);
        if (t == NCTA_A - 1) {
            g_bar_count = 0;
            __threadfence();
            atomicExch(&g_bar_gen, gen + 1u);
        } else {
            while (*(volatile unsigned*)&g_bar_gen == gen) { __nanosleep(32); }
        }
        __threadfence();
    }
    __syncthreads();
}

// ---------------------------------------------------------------------------
// stok: token fed at step t for batch b  ->  g_stok[t*4+b]
// ---------------------------------------------------------------------------
__global__ void stok_kernel(const int* __restrict__ iseq,
                            const int* __restrict__ tgt) {
    int idx = blockIdx.x * 256 + threadIdx.x;
    if (idx < MDIM) {
        int t = idx >> 2, b = idx & 3;
        g_stok[idx] = (t == 0) ? iseq[b * TDIM] : tgt[b * TDIM + t - 1];
    }
}

// ---------------------------------------------------------------------------
// gi GEMM (fp32): g_gi[m][n] = emb[stok[m]] . Wih[n]   (m=t*4+b, n=g*768+j)
// Tile 64x128x32, 256 threads, f32x2 FFMA (R3-proven structure + A gather).
// ---------------------------------------------------------------------------
#define GIM 64
#define GIN 128
#define GIK 32

__global__ void __launch_bounds__(256)
gi_kernel(const float* __restrict__ emb, const float* __restrict__ Wih) {
    __shared__ float sA[GIK][GIM];
    __shared__ float sW[GIK][GIN];
    __shared__ int stk[GIM];

    const int tid = threadIdx.x;
    const int m0 = blockIdx.x * GIM;
    const int n0 = blockIdx.y * GIN;
    const int tm = tid & 15;
    const int tn = tid >> 4;

    if (tid < GIM) stk[tid] = g_stok[m0 + tid];
    __syncthreads();

    ull c2[4][4];
#pragma unroll
    for (int i = 0; i < 4; ++i)
#pragma unroll
        for (int jj = 0; jj < 4; ++jj) c2[i][jj] = 0ULL;

    for (int kc = 0; kc < HDIM / GIK; ++kc) {
        const int kbase = kc * GIK;
#pragma unroll
        for (int q = 0; q < 2; ++q) {
            int idx = q * 256 + tid;
            int m = idx & 63;
            int k4 = (idx >> 6) * 4;
            float4 a = *(const float4*)(emb + (size_t)stk[m] * HDIM + kbase + k4);
            sA[k4 + 0][m] = a.x; sA[k4 + 1][m] = a.y;
            sA[k4 + 2][m] = a.z; sA[k4 + 3][m] = a.w;
        }
#pragma unroll
        for (int q = 0; q < 4; ++q) {
            int idx = q * 256 + tid;
            int n = idx & 127;
            int k4 = (idx >> 7) * 4;
            float4 w = *(const float4*)(Wih + (size_t)(n0 + n) * HDIM + kbase + k4);
            sW[k4 + 0][n] = w.x; sW[k4 + 1][n] = w.y;
            sW[k4 + 2][n] = w.z; sW[k4 + 3][n] = w.w;
        }
        __syncthreads();

#pragma unroll 8
        for (int kk = 0; kk < GIK; ++kk) {
            float4 a4 = *(const float4*)(&sA[kk][tm * 4]);
            ulonglong2 wA = *(const ulonglong2*)(&sW[kk][tn * 8]);
            ulonglong2 wB = *(const ulonglong2*)(&sW[kk][tn * 8 + 4]);
            ull a2[4];
            a2[0] = pack2(a4.x, a4.x);
            a2[1] = pack2(a4.y, a4.y);
            a2[2] = pack2(a4.z, a4.z);
            a2[3] = pack2(a4.w, a4.w);
#pragma unroll
            for (int i = 0; i < 4; ++i) {
                c2[i][0] = fma2(a2[i], wA.x, c2[i][0]);
                c2[i][1] = fma2(a2[i], wA.y, c2[i][1]);
                c2[i][2] = fma2(a2[i], wB.x, c2[i][2]);
                c2[i][3] = fma2(a2[i], wB.y, c2[i][3]);
            }
        }
        __syncthreads();
    }

#pragma unroll
    for (int i = 0; i < 4; ++i) {
        float* orow = g_gi + (size_t)(m0 + tm * 4 + i) * GDIM + n0 + tn * 8;
#pragma unroll
        for (int jj = 0; jj < 4; ++jj)
            *(float2*)(orow + jj * 2) = unpack2(c2[i][jj]);
    }
}

// ---------------------------------------------------------------------------
// GRU recurrence: 96 CTAs x 512 threads (16 warps). Warp w handles
// j = bx*8 + (w&7), k-half = (w>>3)*384. Whh rows live in REGISTERS.
// Per step: gh dots (regs x g_h), warp reduce, cross-half combine in smem,
// lanes 0-3 (b=lane) compute gates and write g_h + g_Hbf(bf16).
// ---------------------------------------------------------------------------
__global__ void __launch_bounds__(512, 1)
gru_kernel(const int* __restrict__ lyr, const float* __restrict__ tfidf_,
           const float* __restrict__ lyrW, const float* __restrict__ lyrb,
           const float* __restrict__ Whh, const float* __restrict__ bih,
           const float* __restrict__ bhh) {
    __shared__ float spart[16][12];

    const int tid = threadIdx.x;
    const int lane = tid & 31;
    const int w = tid >> 5;
    const int j = blockIdx.x * 8 + (w & 7);
    const int half = w >> 3;
    const int kb = half * 384 + lane * 4;

    // gate biases (used by lanes 0-3 of warps 0-7)
    const float bIRH = bih[j] + bhh[j];
    const float bIZH = bih[HDIM + j] + bhh[HDIM + j];
    const float bIN  = bih[2 * HDIM + j];
    const float bHN  = bhh[2 * HDIM + j];

    // Whh rows in registers: 3 gates x 3 k-chunks x 16B
    ulonglong2 whv[3][3];
#pragma unroll
    for (int g = 0; g < 3; ++g)
#pragma unroll
        for (int it = 0; it < 3; ++it)
            whv[g][it] = *(const ulonglong2*)(
                Whh + ((size_t)g * HDIM + j) * HDIM + kb + it * 128);

    // ---- h0[b][j] = dot(tfidf[lyr[b]], lyr_W[j]) + lyr_b[j]  (half==0) ----
    if (half == 0) {
        const float* wrow = lyrW + (size_t)j * TFDIM;
#pragma unroll
        for (int b = 0; b < BDIM; ++b) {
            const float* trow = tfidf_ + (size_t)lyr[b] * TFDIM;
            float acc = 0.0f;
#pragma unroll
            for (int it = 0; it < 8; ++it) {
                int k = it * 128 + lane * 4;
                float4 tv = *(const float4*)(trow + k);
                float4 wv = *(const float4*)(wrow + k);
                acc = fmaf(tv.x, wv.x, acc);
                acc = fmaf(tv.y, wv.y, acc);
                acc = fmaf(tv.z, wv.z, acc);
                acc = fmaf(tv.w, wv.w, acc);
            }
            acc = wredsum(acc);
            if (lane == 0) g_h[0][b * HDIM + j] = acc + lyrb[j];
        }
    }
    grid_barrier();

    for (int t = 0; t < TDIM; ++t) {
        const int rb = t & 1, wb = rb ^ 1;

        // prefetch this step's x-gates (independent of h)
        float gvR, gvZ, gvN;
        if (w < 8 && lane < 4) {
            const float* gp = g_gi + (size_t)(t * 4 + lane) * GDIM + j;
            gvR = gp[0];
            gvZ = gp[HDIM];
            gvN = gp[2 * HDIM];
        }

        // gh partial dots from register weights
        ull aR[4], aZ[4], aN[4];
#pragma unroll
        for (int b = 0; b < BDIM; ++b) { aR[b] = 0; aZ[b] = 0; aN[b] = 0; }
#pragma unroll
        for (int it = 0; it < 3; ++it) {
            const float* hb = g_h[rb] + kb + it * 128;
#pragma unroll
            for (int b = 0; b < BDIM; ++b) {
                ulonglong2 h = *(const ulonglong2*)(hb + b * HDIM);
                aR[b] = fma2(whv[0][it].x, h.x, aR[b]);
                aR[b] = fma2(whv[0][it].y, h.y, aR[b]);
                aZ[b] = fma2(whv[1][it].x, h.x, aZ[b]);
                aZ[b] = fma2(whv[1][it].y, h.y, aZ[b]);
                aN[b] = fma2(whv[2][it].x, h.x, aN[b]);
                aN[b] = fma2(whv[2][it].y, h.y, aN[b]);
            }
        }

        // intra-warp reduce 12 sums
        float sR[4], sZ[4], sN[4];
#pragma unroll
        for (int b = 0; b < BDIM; ++b) {
            float2 v;
            v = unpack2(aR[b]); sR[b] = wredsum(v.x + v.y);
            v = unpack2(aZ[b]); sZ[b] = wredsum(v.x + v.y);
            v = unpack2(aN[b]); sN[b] = wredsum(v.x + v.y);
        }
        if (lane == 0) {
#pragma unroll
            for (int b = 0; b < BDIM; ++b) {
                spart[w][b * 3 + 0] = sR[b];
                spart[w][b * 3 + 1] = sZ[b];
                spart[w][b * 3 + 2] = sN[b];
            }
        }
        __syncthreads();

        if (w < 8 && lane < 4) {
            const int b = lane;
            float ghr = spart[w][b * 3 + 0] + spart[w + 8][b * 3 + 0];
            float ghz = spart[w][b * 3 + 1] + spart[w + 8][b * 3 + 1];
            float ghn = spart[w][b * 3 + 2] + spart[w + 8][b * 3 + 2];
            float r = sigmoidf_(gvR + bIRH + ghr);
            float z = sigmoidf_(gvZ + bIZH + ghz);
            float n = tanhf(gvN + bIN + r * (ghn + bHN));
            float hp = g_h[rb][b * HDIM + j];
            float hn_ = (1.0f - z) * n + z * hp;
            g_h[wb][b * HDIM + j] = hn_;
            g_Hbf[(size_t)(b * TDIM + t) * HDIM + j] = __float2bfloat16(hn_);
        }
        grid_barrier();
    }
}

// ---------------------------------------------------------------------------
// fp32 -> bf16 convert of out_W only (H states already written as bf16).
// ---------------------------------------------------------------------------
__global__ void __launch_bounds__(256)
convert_kernel(const float* __restrict__ outW) {
    const size_t i0 = (size_t)blockIdx.x * blockDim.x + threadIdx.x;
    const size_t stride = (size_t)gridDim.x * blockDim.x;
    const size_t NW4 = (size_t)VDIM * HDIM / 4;
    for (size_t k = i0; k < NW4; k += stride) {
        float4 v = ((const float4*)outW)[k];
        ((__nv_bfloat162*)g_Wbf)[k * 2]     = __floats2bfloat162_rn(v.x, v.y);
        ((__nv_bfloat162*)g_Wbf)[k * 2 + 1] = __floats2bfloat162_rn(v.z, v.w);
    }
}

// ---------------------------------------------------------------------------
// Phase B: HMMA GEMM  C[2048,32000] = Hbf @ Wbf.T + out_b  (unchanged, R5 pass)
// ---------------------------------------------------------------------------
#define TM 128
#define TN 128
#define TK 32
#define NCHUNK (HDIM / TK)       // 24
#define SPAD 40                  // bf16 per smem row (80B stride)

__device__ __forceinline__ void ldmx4(uint32_t* r, uint32_t addr) {
    asm volatile("ldmatrix.sync.aligned.m8n8.x4.shared.b16 {%0,%1,%2,%3}, [%4];"
                 : "=r"(r[0]), "=r"(r[1]), "=r"(r[2]), "=r"(r[3]) : "r"(addr));
}
__device__ __forceinline__ void hmma(float* d, const uint32_t* a,
                                     const uint32_t* b) {
    asm volatile(
        "mma.sync.aligned.m16n8k16.row.col.f32.bf16.bf16.f32 "
        "{%0,%1,%2,%3}, {%4,%5,%6,%7}, {%8,%9}, {%0,%1,%2,%3};"
        : "+f"(d[0]), "+f"(d[1]), "+f"(d[2]), "+f"(d[3])
        : "r"(a[0]), "r"(a[1]), "r"(a[2]), "r"(a[3]), "r"(b[0]), "r"(b[1]));
}

__global__ void __launch_bounds__(256, 2)
gemm_kernel(const float* __restrict__ outb, float* __restrict__ out) {
    __shared__ __nv_bfloat16 sA[2][TM][SPAD];
    __shared__ __nv_bfloat16 sB[2][TN][SPAD];
    __shared__ float sbias[TN];

    const int tid = threadIdx.x;
    const int lane = tid & 31;
    const int wid = tid >> 5;
    const int wm = wid & 3;
    const int wn = wid >> 2;
    const size_t m0 = (size_t)blockIdx.x * TM;
    const size_t n0 = (size_t)blockIdx.y * TN;

    for (int i = tid; i < TN; i += 256) sbias[i] = outb[n0 + i];

    const int grow = tid >> 2;
    const int gseg = tid & 3;

    const __nv_bfloat16* gA = g_Hbf + (m0 + grow) * HDIM + gseg * 8;
    const __nv_bfloat16* gB = g_Wbf + (n0 + grow) * HDIM + gseg * 8;

    {
#pragma unroll
        for (int q = 0; q < 2; ++q) {
            uint4 a = *(const uint4*)(gA + q * 64 * HDIM);
            uint4 b = *(const uint4*)(gB + q * 64 * HDIM);
            *(uint4*)(&sA[0][grow + q * 64][gseg * 8]) = a;
            *(uint4*)(&sB[0][grow + q * 64][gseg * 8]) = b;
        }
    }
    __syncthreads();

    float acc[2][8][4];
#pragma unroll
    for (int am = 0; am < 2; ++am)
#pragma unroll
        for (int bn = 0; bn < 8; ++bn)
#pragma unroll
            for (int q = 0; q < 4; ++q) acc[am][bn][q] = 0.0f;

    const int a_r = lane & 15, a_c = (lane >> 4) * 8;
    const int b_g = lane >> 3;
    const int b_r = ((b_g >> 1) << 3) + (lane & 7);
    const int b_c = (b_g & 1) * 8;

    for (int c = 0; c < NCHUNK; ++c) {
        const int p = c & 1;
        const bool more = (c + 1) < NCHUNK;
        uint4 pa0, pa1, pb0, pb1;
        if (more) {
            const __nv_bfloat16* sa = gA + (size_t)(c + 1) * TK;
            const __nv_bfloat16* sb2 = gB + (size_t)(c + 1) * TK;
            pa0 = *(const uint4*)(sa);
            pa1 = *(const uint4*)(sa + 64 * HDIM);
            pb0 = *(const uint4*)(sb2);
            pb1 = *(const uint4*)(sb2 + 64 * HDIM);
        }

#pragma unroll
        for (int ks = 0; ks < 2; ++ks) {
            const int k8 = ks * 16;
            uint32_t afr[2][4], bfr[4][4];
#pragma unroll
            for (int am = 0; am < 2; ++am)
                ldmx4(afr[am],
                      smem_u32(&sA[p][wm * 32 + am * 16 + a_r][k8 + a_c]));
#pragma unroll
            for (int bg = 0; bg < 4; ++bg)
                ldmx4(bfr[bg],
                      smem_u32(&sB[p][wn * 64 + bg * 16 + b_r][k8 + b_c]));
#pragma unroll
            for (int am = 0; am < 2; ++am)
#pragma unroll
                for (int bn = 0; bn < 8; ++bn)
                    hmma(acc[am][bn], afr[am], &bfr[bn >> 1][(bn & 1) * 2]);
        }

        if (more) {
            *(uint4*)(&sA[p ^ 1][grow][gseg * 8]) = pa0;
            *(uint4*)(&sA[p ^ 1][grow + 64][gseg * 8]) = pa1;
            *(uint4*)(&sB[p ^ 1][grow][gseg * 8]) = pb0;
            *(uint4*)(&sB[p ^ 1][grow + 64][gseg * 8]) = pb1;
        }
        __syncthreads();
    }

#pragma unroll
    for (int am = 0; am < 2; ++am) {
#pragma unroll
        for (int half = 0; half < 2; ++half) {
            const size_t row = m0 + wm * 32 + am * 16 + half * 8 + (lane >> 2);
            float* orow = out + row * VDIM + n0 + wn * 64 + (lane & 3) * 2;
#pragma unroll
            for (int bn = 0; bn < 8; ++bn) {
                const int colL = wn * 64 + bn * 8 + (lane & 3) * 2;
                float2 v;
                v.x = acc[am][bn][half * 2 + 0] + sbias[colL];
                v.y = acc[am][bn][half * 2 + 1] + sbias[colL + 1];
                *(float2*)(orow + bn * 8) = v;
            }
        }
    }
}

// ---------------------------------------------------------------------------
// Row log_softmax, row cached in 125 KB smem: 1 DRAM read + 1 DRAM write.
// ---------------------------------------------------------------------------
#define LSM_SMEM (VDIM * 4)

__global__ void __launch_bounds__(512)
logsoftmax_kernel(float* __restrict__ out) {
    extern __shared__ float srow[];
    __shared__ float red[16];
    const int tid = threadIdx.x;
    const int lane = tid & 31;
    const int wid = tid >> 5;
    float* x = out + (size_t)blockIdx.x * VDIM;

    float m = -3.4e38f;
    for (int i = tid; i < VDIM / 4; i += 512) {
        float4 v = ((const float4*)x)[i];
        ((float4*)srow)[i] = v;
        m = fmaxf(fmaxf(m, fmaxf(v.x, v.y)), fmaxf(v.z, v.w));
    }
    m = wredmax(m);
    if (lane == 0) red[wid] = m;
    __syncthreads();
#pragma unroll
    for (int q = 0; q < 16; ++q) m = fmaxf(m, red[q]);
    __syncthreads();

    float s = 0.0f;
    for (int i = tid; i < VDIM / 4; i += 512) {
        float4 v = ((const float4*)srow)[i];
        s += __expf(v.x - m) + __expf(v.y - m) +
             __expf(v.z - m) + __expf(v.w - m);
    }
    s = wredsum(s);
    if (lane == 0) red[wid] = s;
    __syncthreads();
    float tot = 0.0f;
#pragma unroll
    for (int q = 0; q < 16; ++q) tot += red[q];

    const float lse = m + logf(tot);
    for (int i = tid; i < VDIM / 4; i += 512) {
        float4 v = ((const float4*)srow)[i];
        v.x -= lse; v.y -= lse; v.z -= lse; v.w -= lse;
        ((float4*)x)[i] = v;
    }
}

// ---------------------------------------------------------------------------
// Tail: h_last and attentions (= ones).
// ---------------------------------------------------------------------------
__global__ void tail_kernel(float* __restrict__ out) {
    const int i = blockIdx.x * 256 + threadIdx.x;
    const size_t HOFF = (size_t)MDIM * VDIM;
    if (i < BDIM * HDIM) out[HOFF + i] = g_h[0][i];
    if (i < BDIM * TDIM) out[HOFF + BDIM * HDIM + i] = 1.0f;
}

// ---------------------------------------------------------------------------
extern "C" void kernel_launch(void* const* d_in, const int* in_sizes, int n_in,
                              void* d_out, int out_size) {
    const int*   lyr   = (const int*)d_in[0];
    const int*   iseq  = (const int*)d_in[1];
    const int*   tgt   = (const int*)d_in[2];
    const float* emb   = (const float*)d_in[3];
    // d_in[4..9]: Wa, ba, Ua, ub, Va, vb -> dead (softmax over length-1 axis)
    const float* tfidf_ = (const float*)d_in[10];
    const float* lyrW  = (const float*)d_in[11];
    const float* lyrb  = (const float*)d_in[12];
    const float* Wih   = (const float*)d_in[13];
    // d_in[14] Whh, 15 bih, 16 bhh
    const float* Whh   = (const float*)d_in[14];
    const float* bih   = (const float*)d_in[15];
    const float* bhh   = (const float*)d_in[16];
    const float* outW  = (const float*)d_in[17];
    const float* outb  = (const float*)d_in[18];
    float* out = (float*)d_out;

    cudaFuncSetAttribute(logsoftmax_kernel,
                         cudaFuncAttributeMaxDynamicSharedMemorySize,
                         LSM_SMEM + 1024);

    stok_kernel<<<(MDIM + 255) / 256, 256>>>(iseq, tgt);

    dim3 gi_grid(MDIM / GIM, GDIM / GIN);    // (32, 18)
    gi_kernel<<<gi_grid, 256>>>(emb, Wih);

    gru_kernel<<<NCTA_A, 512>>>(lyr, tfidf_, lyrW, lyrb, Whh, bih, bhh);

    convert_kernel<<<1024, 256>>>(outW);

    dim3 gg(MDIM / TM, VDIM / TN);           // (16, 250)
    gemm_kernel<<<gg, 256>>>(outb, out);

    logsoftmax_kernel<<<MDIM, 512, LSM_SMEM>>>(out);

    tail_kernel<<<(BDIM * TDIM + 255) / 256 + 12, 256>>>(out);
}

// round 7
// speedup vs baseline: 2.9673x; 1.0262x over previous
#include <cuda_runtime.h>
#include <cuda_bf16.h>
#include <cstdint>

// ---------------------------------------------------------------------------
// ConditionedAttnGRUDecoder  (H=768, V=32000, TF=1024, B=4, T=512)
//  * softmax over length-1 axis == 1 -> ctx == h_prev, attentions == ones,
//    Wa/ba/Ua/ub/Va/vb are dead inputs.
//  * log_softmax twice == once.
//  * gi = x@Wih^T precomputed for ALL steps (tokens known upfront).
//  * recurrent loop: only gh = h@Whh^T, with Whh in REGISTERS.
//  * output projection: ONE bf16 HMMA GEMM (portable mma.sync m16n8k16).
// ---------------------------------------------------------------------------

#define HDIM 768
#define BDIM 4
#define TDIM 512
#define TFDIM 1024
#define VDIM 32000
#define MDIM (BDIM * TDIM)       // 2048
#define GDIM (3 * HDIM)          // 2304

#define NCTA_A 96                // GRU CTAs (96 x 16 warps; 2 warps per j)

typedef unsigned long long ull;

// ----------------------------- device scratch ------------------------------
__device__ float g_h[2][BDIM * HDIM];                   // hidden double buffer
__device__ __align__(16) __nv_bfloat16 g_Hbf[(size_t)MDIM * HDIM];
__device__ __align__(16) __nv_bfloat16 g_Wbf[(size_t)VDIM * HDIM];
__device__ __align__(16) float g_gi[(size_t)MDIM * GDIM];   // precomputed x-gates
__device__ int g_stok[MDIM];                            // token per (t*4+b)
__device__ unsigned g_bar_count = 0;
__device__ unsigned g_bar_gen = 0;

// ----------------------------- helpers -------------------------------------
__device__ __forceinline__ ull fma2(ull a, ull b, ull c) {
    ull d;
    asm("fma.rn.f32x2 %0, %1, %2, %3;" : "=l"(d) : "l"(a), "l"(b), "l"(c));
    return d;
}
__device__ __forceinline__ ull pack2(float x, float y) {
    ull r;
    asm("mov.b64 %0, {%1, %2};" : "=l"(r) : "f"(x), "f"(y));
    return r;
}
__device__ __forceinline__ float2 unpack2(ull v) {
    float2 r;
    asm("mov.b64 {%0, %1}, %2;" : "=f"(r.x), "=f"(r.y) : "l"(v));
    return r;
}
__device__ __forceinline__ float wredsum(float v) {
#pragma unroll
    for (int o = 16; o; o >>= 1) v += __shfl_xor_sync(0xffffffffu, v, o);
    return v;
}
__device__ __forceinline__ float wredmax(float v) {
#pragma unroll
    for (int o = 16; o; o >>= 1) v = fmaxf(v, __shfl_xor_sync(0xffffffffu, v, o));
    return v;
}
__device__ __forceinline__ float sigmoidf_(float x) {
    return 1.0f / (1.0f + __expf(-x));
}
__device__ __forceinline__ uint32_t smem_u32(const void* p) {
    uint32_t a;
    asm("{ .reg .u64 t; cvta.to.shared.u64 t, %1; cvt.u32.u64 %0, t; }"
        : "=r"(a) : "l"(p));
    return a;
}

// grid-wide barrier (all NCTA_A CTAs resident)
__device__ __forceinline__ void grid_barrier() {
    __syncthreads();
    if (threadIdx.x == 0) {
        __threadfence();
        unsigned gen = *(volatile unsigned*)&g_bar_gen;
        unsigned t = atomicAdd(&g_bar_count, 1u);
        if (t == NCTA_A - 1) {
            g_bar_count = 0;
            __threadfence();
            atomicExch(&g_bar_gen, gen + 1u);
        } else {
            while (*(volatile unsigned*)&g_bar_gen == gen) { __nanosleep(32); }
        }
        __threadfence();
    }
    __syncthreads();
}

// ---------------------------------------------------------------------------
// stok: token fed at step t for batch b  ->  g_stok[t*4+b]
// ---------------------------------------------------------------------------
__global__ void stok_kernel(const int* __restrict__ iseq,
                            const int* __restrict__ tgt) {
    int idx = blockIdx.x * 256 + threadIdx.x;
    if (idx < MDIM) {
        int t = idx >> 2, b = idx & 3;
        g_stok[idx] = (t == 0) ? iseq[b * TDIM] : tgt[b * TDIM + t - 1];
    }
}

// ---------------------------------------------------------------------------
// gi GEMM (fp32): g_gi[m][n] = emb[stok[m]] . Wih[n]   (m=t*4+b, n=g*768+j)
// Tile 64x128x32, 256 threads, f32x2 FFMA (R3-proven structure + A gather).
// ---------------------------------------------------------------------------
#define GIM 64
#define GIN 128
#define GIK 32

__global__ void __launch_bounds__(256)
gi_kernel(const float* __restrict__ emb, const float* __restrict__ Wih) {
    __shared__ float sA[GIK][GIM];
    __shared__ float sW[GIK][GIN];
    __shared__ int stk[GIM];

    const int tid = threadIdx.x;
    const int m0 = blockIdx.x * GIM;
    const int n0 = blockIdx.y * GIN;
    const int tm = tid & 15;
    const int tn = tid >> 4;

    if (tid < GIM) stk[tid] = g_stok[m0 + tid];
    __syncthreads();

    ull c2[4][4];
#pragma unroll
    for (int i = 0; i < 4; ++i)
#pragma unroll
        for (int jj = 0; jj < 4; ++jj) c2[i][jj] = 0ULL;

    for (int kc = 0; kc < HDIM / GIK; ++kc) {
        const int kbase = kc * GIK;
#pragma unroll
        for (int q = 0; q < 2; ++q) {
            int idx = q * 256 + tid;
            int m = idx & 63;
            int k4 = (idx >> 6) * 4;
            float4 a = *(const float4*)(emb + (size_t)stk[m] * HDIM + kbase + k4);
            sA[k4 + 0][m] = a.x; sA[k4 + 1][m] = a.y;
            sA[k4 + 2][m] = a.z; sA[k4 + 3][m] = a.w;
        }
#pragma unroll
        for (int q = 0; q < 4; ++q) {
            int idx = q * 256 + tid;
            int n = idx & 127;
            int k4 = (idx >> 7) * 4;
            float4 w = *(const float4*)(Wih + (size_t)(n0 + n) * HDIM + kbase + k4);
            sW[k4 + 0][n] = w.x; sW[k4 + 1][n] = w.y;
            sW[k4 + 2][n] = w.z; sW[k4 + 3][n] = w.w;
        }
        __syncthreads();

#pragma unroll 8
        for (int kk = 0; kk < GIK; ++kk) {
            float4 a4 = *(const float4*)(&sA[kk][tm * 4]);
            ulonglong2 wA = *(const ulonglong2*)(&sW[kk][tn * 8]);
            ulonglong2 wB = *(const ulonglong2*)(&sW[kk][tn * 8 + 4]);
            ull a2[4];
            a2[0] = pack2(a4.x, a4.x);
            a2[1] = pack2(a4.y, a4.y);
            a2[2] = pack2(a4.z, a4.z);
            a2[3] = pack2(a4.w, a4.w);
#pragma unroll
            for (int i = 0; i < 4; ++i) {
                c2[i][0] = fma2(a2[i], wA.x, c2[i][0]);
                c2[i][1] = fma2(a2[i], wA.y, c2[i][1]);
                c2[i][2] = fma2(a2[i], wB.x, c2[i][2]);
                c2[i][3] = fma2(a2[i], wB.y, c2[i][3]);
            }
        }
        __syncthreads();
    }

#pragma unroll
    for (int i = 0; i < 4; ++i) {
        float* orow = g_gi + (size_t)(m0 + tm * 4 + i) * GDIM + n0 + tn * 8;
#pragma unroll
        for (int jj = 0; jj < 4; ++jj)
            *(float2*)(orow + jj * 2) = unpack2(c2[i][jj]);
    }
}

// ---------------------------------------------------------------------------
// GRU recurrence: 96 CTAs x 512 threads (16 warps). Warp w handles
// j = bx*8 + (w&7), k-half = (w>>3)*384. Whh rows live in REGISTERS.
// Per step: gh dots (regs x g_h), warp reduce, cross-half combine in smem,
// lanes 0-3 (b=lane) compute gates and write g_h + g_Hbf(bf16).
// ---------------------------------------------------------------------------
__global__ void __launch_bounds__(512, 1)
gru_kernel(const int* __restrict__ lyr, const float* __restrict__ tfidf_,
           const float* __restrict__ lyrW, const float* __restrict__ lyrb,
           const float* __restrict__ Whh, const float* __restrict__ bih,
           const float* __restrict__ bhh) {
    __shared__ float spart[16][12];

    const int tid = threadIdx.x;
    const int lane = tid & 31;
    const int w = tid >> 5;
    const int j = blockIdx.x * 8 + (w & 7);
    const int half = w >> 3;
    const int kb = half * 384 + lane * 4;

    // gate biases (used by lanes 0-3 of warps 0-7)
    const float bIRH = bih[j] + bhh[j];
    const float bIZH = bih[HDIM + j] + bhh[HDIM + j];
    const float bIN  = bih[2 * HDIM + j];
    const float bHN  = bhh[2 * HDIM + j];

    // Whh rows in registers: 3 gates x 3 k-chunks x 16B
    ulonglong2 whv[3][3];
#pragma unroll
    for (int g = 0; g < 3; ++g)
#pragma unroll
        for (int it = 0; it < 3; ++it)
            whv[g][it] = *(const ulonglong2*)(
                Whh + ((size_t)g * HDIM + j) * HDIM + kb + it * 128);

    // ---- h0[b][j] = dot(tfidf[lyr[b]], lyr_W[j]) + lyr_b[j]  (half==0) ----
    if (half == 0) {
        const float* wrow = lyrW + (size_t)j * TFDIM;
#pragma unroll
        for (int b = 0; b < BDIM; ++b) {
            const float* trow = tfidf_ + (size_t)lyr[b] * TFDIM;
            float acc = 0.0f;
#pragma unroll
            for (int it = 0; it < 8; ++it) {
                int k = it * 128 + lane * 4;
                float4 tv = *(const float4*)(trow + k);
                float4 wv = *(const float4*)(wrow + k);
                acc = fmaf(tv.x, wv.x, acc);
                acc = fmaf(tv.y, wv.y, acc);
                acc = fmaf(tv.z, wv.z, acc);
                acc = fmaf(tv.w, wv.w, acc);
            }
            acc = wredsum(acc);
            if (lane == 0) g_h[0][b * HDIM + j] = acc + lyrb[j];
        }
    }
    grid_barrier();

    for (int t = 0; t < TDIM; ++t) {
        const int rb = t & 1, wb = rb ^ 1;

        // prefetch this step's x-gates (independent of h)
        float gvR, gvZ, gvN;
        if (w < 8 && lane < 4) {
            const float* gp = g_gi + (size_t)(t * 4 + lane) * GDIM + j;
            gvR = gp[0];
            gvZ = gp[HDIM];
            gvN = gp[2 * HDIM];
        }

        // gh partial dots from register weights
        ull aR[4], aZ[4], aN[4];
#pragma unroll
        for (int b = 0; b < BDIM; ++b) { aR[b] = 0; aZ[b] = 0; aN[b] = 0; }
#pragma unroll
        for (int it = 0; it < 3; ++it) {
            const float* hb = g_h[rb] + kb + it * 128;
#pragma unroll
            for (int b = 0; b < BDIM; ++b) {
                ulonglong2 h = *(const ulonglong2*)(hb + b * HDIM);
                aR[b] = fma2(whv[0][it].x, h.x, aR[b]);
                aR[b] = fma2(whv[0][it].y, h.y, aR[b]);
                aZ[b] = fma2(whv[1][it].x, h.x, aZ[b]);
                aZ[b] = fma2(whv[1][it].y, h.y, aZ[b]);
                aN[b] = fma2(whv[2][it].x, h.x, aN[b]);
                aN[b] = fma2(whv[2][it].y, h.y, aN[b]);
            }
        }

        // intra-warp reduce 12 sums
        float sR[4], sZ[4], sN[4];
#pragma unroll
        for (int b = 0; b < BDIM; ++b) {
            float2 v;
            v = unpack2(aR[b]); sR[b] = wredsum(v.x + v.y);
            v = unpack2(aZ[b]); sZ[b] = wredsum(v.x + v.y);
            v = unpack2(aN[b]); sN[b] = wredsum(v.x + v.y);
        }
        if (lane == 0) {
#pragma unroll
            for (int b = 0; b < BDIM; ++b) {
                spart[w][b * 3 + 0] = sR[b];
                spart[w][b * 3 + 1] = sZ[b];
                spart[w][b * 3 + 2] = sN[b];
            }
        }
        __syncthreads();

        if (w < 8 && lane < 4) {
            const int b = lane;
            float ghr = spart[w][b * 3 + 0] + spart[w + 8][b * 3 + 0];
            float ghz = spart[w][b * 3 + 1] + spart[w + 8][b * 3 + 1];
            float ghn = spart[w][b * 3 + 2] + spart[w + 8][b * 3 + 2];
            float r = sigmoidf_(gvR + bIRH + ghr);
            float z = sigmoidf_(gvZ + bIZH + ghz);
            float n = tanhf(gvN + bIN + r * (ghn + bHN));
            float hp = g_h[rb][b * HDIM + j];
            float hn_ = (1.0f - z) * n + z * hp;
            g_h[wb][b * HDIM + j] = hn_;
            g_Hbf[(size_t)(b * TDIM + t) * HDIM + j] = __float2bfloat16(hn_);
        }
        grid_barrier();
    }
}

// ---------------------------------------------------------------------------
// fp32 -> bf16 convert of out_W only (H states already written as bf16).
// ---------------------------------------------------------------------------
__global__ void __launch_bounds__(256)
convert_kernel(const float* __restrict__ outW) {
    const size_t i0 = (size_t)blockIdx.x * blockDim.x + threadIdx.x;
    const size_t stride = (size_t)gridDim.x * blockDim.x;
    const size_t NW4 = (size_t)VDIM * HDIM / 4;
    for (size_t k = i0; k < NW4; k += stride) {
        float4 v = ((const float4*)outW)[k];
        ((__nv_bfloat162*)g_Wbf)[k * 2]     = __floats2bfloat162_rn(v.x, v.y);
        ((__nv_bfloat162*)g_Wbf)[k * 2 + 1] = __floats2bfloat162_rn(v.z, v.w);
    }
}

// ---------------------------------------------------------------------------
// Phase B: HMMA GEMM  C[2048,32000] = Hbf @ Wbf.T + out_b  (unchanged, R5 pass)
// ---------------------------------------------------------------------------
#define TM 128
#define TN 128
#define TK 32
#define NCHUNK (HDIM / TK)       // 24
#define SPAD 40                  // bf16 per smem row (80B stride)

__device__ __forceinline__ void ldmx4(uint32_t* r, uint32_t addr) {
    asm volatile("ldmatrix.sync.aligned.m8n8.x4.shared.b16 {%0,%1,%2,%3}, [%4];"
                 : "=r"(r[0]), "=r"(r[1]), "=r"(r[2]), "=r"(r[3]) : "r"(addr));
}
__device__ __forceinline__ void hmma(float* d, const uint32_t* a,
                                     const uint32_t* b) {
    asm volatile(
        "mma.sync.aligned.m16n8k16.row.col.f32.bf16.bf16.f32 "
        "{%0,%1,%2,%3}, {%4,%5,%6,%7}, {%8,%9}, {%0,%1,%2,%3};"
        : "+f"(d[0]), "+f"(d[1]), "+f"(d[2]), "+f"(d[3])
        : "r"(a[0]), "r"(a[1]), "r"(a[2]), "r"(a[3]), "r"(b[0]), "r"(b[1]));
}

__global__ void __launch_bounds__(256, 2)
gemm_kernel(const float* __restrict__ outb, float* __restrict__ out) {
    __shared__ __nv_bfloat16 sA[2][TM][SPAD];
    __shared__ __nv_bfloat16 sB[2][TN][SPAD];
    __shared__ float sbias[TN];

    const int tid = threadIdx.x;
    const int lane = tid & 31;
    const int wid = tid >> 5;
    const int wm = wid & 3;
    const int wn = wid >> 2;
    const size_t m0 = (size_t)blockIdx.x * TM;
    const size_t n0 = (size_t)blockIdx.y * TN;

    for (int i = tid; i < TN; i += 256) sbias[i] = outb[n0 + i];

    const int grow = tid >> 2;
    const int gseg = tid & 3;

    const __nv_bfloat16* gA = g_Hbf + (m0 + grow) * HDIM + gseg * 8;
    const __nv_bfloat16* gB = g_Wbf + (n0 + grow) * HDIM + gseg * 8;

    {
#pragma unroll
        for (int q = 0; q < 2; ++q) {
            uint4 a = *(const uint4*)(gA + q * 64 * HDIM);
            uint4 b = *(const uint4*)(gB + q * 64 * HDIM);
            *(uint4*)(&sA[0][grow + q * 64][gseg * 8]) = a;
            *(uint4*)(&sB[0][grow + q * 64][gseg * 8]) = b;
        }
    }
    __syncthreads();

    float acc[2][8][4];
#pragma unroll
    for (int am = 0; am < 2; ++am)
#pragma unroll
        for (int bn = 0; bn < 8; ++bn)
#pragma unroll
            for (int q = 0; q < 4; ++q) acc[am][bn][q] = 0.0f;

    const int a_r = lane & 15, a_c = (lane >> 4) * 8;
    const int b_g = lane >> 3;
    const int b_r = ((b_g >> 1) << 3) + (lane & 7);
    const int b_c = (b_g & 1) * 8;

    for (int c = 0; c < NCHUNK; ++c) {
        const int p = c & 1;
        const bool more = (c + 1) < NCHUNK;
        uint4 pa0, pa1, pb0, pb1;
        if (more) {
            const __nv_bfloat16* sa = gA + (size_t)(c + 1) * TK;
            const __nv_bfloat16* sb2 = gB + (size_t)(c + 1) * TK;
            pa0 = *(const uint4*)(sa);
            pa1 = *(const uint4*)(sa + 64 * HDIM);
            pb0 = *(const uint4*)(sb2);
            pb1 = *(const uint4*)(sb2 + 64 * HDIM);
        }

#pragma unroll
        for (int ks = 0; ks < 2; ++ks) {
            const int k8 = ks * 16;
            uint32_t afr[2][4], bfr[4][4];
#pragma unroll
            for (int am = 0; am < 2; ++am)
                ldmx4(afr[am],
                      smem_u32(&sA[p][wm * 32 + am * 16 + a_r][k8 + a_c]));
#pragma unroll
            for (int bg = 0; bg < 4; ++bg)
                ldmx4(bfr[bg],
                      smem_u32(&sB[p][wn * 64 + bg * 16 + b_r][k8 + b_c]));
#pragma unroll
            for (int am = 0; am < 2; ++am)
#pragma unroll
                for (int bn = 0; bn < 8; ++bn)
                    hmma(acc[am][bn], afr[am], &bfr[bn >> 1][(bn & 1) * 2]);
        }

        if (more) {
            *(uint4*)(&sA[p ^ 1][grow][gseg * 8]) = pa0;
            *(uint4*)(&sA[p ^ 1][grow + 64][gseg * 8]) = pa1;
            *(uint4*)(&sB[p ^ 1][grow][gseg * 8]) = pb0;
            *(uint4*)(&sB[p ^ 1][grow + 64][gseg * 8]) = pb1;
        }
        __syncthreads();
    }

#pragma unroll
    for (int am = 0; am < 2; ++am) {
#pragma unroll
        for (int half = 0; half < 2; ++half) {
            const size_t row = m0 + wm * 32 + am * 16 + half * 8 + (lane >> 2);
            float* orow = out + row * VDIM + n0 + wn * 64 + (lane & 3) * 2;
#pragma unroll
            for (int bn = 0; bn < 8; ++bn) {
                const int colL = wn * 64 + bn * 8 + (lane & 3) * 2;
                float2 v;
                v.x = acc[am][bn][half * 2 + 0] + sbias[colL];
                v.y = acc[am][bn][half * 2 + 1] + sbias[colL + 1];
                *(float2*)(orow + bn * 8) = v;
            }
        }
    }
}

// ---------------------------------------------------------------------------
// Row log_softmax, row cached in 125 KB smem: 1 DRAM read + 1 DRAM write.
// ---------------------------------------------------------------------------
#define LSM_SMEM (VDIM * 4)

__global__ void __launch_bounds__(512)
logsoftmax_kernel(float* __restrict__ out) {
    extern __shared__ float srow[];
    __shared__ float red[16];
    const int tid = threadIdx.x;
    const int lane = tid & 31;
    const int wid = tid >> 5;
    float* x = out + (size_t)blockIdx.x * VDIM;

    float m = -3.4e38f;
    for (int i = tid; i < VDIM / 4; i += 512) {
        float4 v = ((const float4*)x)[i];
        ((float4*)srow)[i] = v;
        m = fmaxf(fmaxf(m, fmaxf(v.x, v.y)), fmaxf(v.z, v.w));
    }
    m = wredmax(m);
    if (lane == 0) red[wid] = m;
    __syncthreads();
#pragma unroll
    for (int q = 0; q < 16; ++q) m = fmaxf(m, red[q]);
    __syncthreads();

    float s = 0.0f;
    for (int i = tid; i < VDIM / 4; i += 512) {
        float4 v = ((const float4*)srow)[i];
        s += __expf(v.x - m) + __expf(v.y - m) +
             __expf(v.z - m) + __expf(v.w - m);
    }
    s = wredsum(s);
    if (lane == 0) red[wid] = s;
    __syncthreads();
    float tot = 0.0f;
#pragma unroll
    for (int q = 0; q < 16; ++q) tot += red[q];

    const float lse = m + logf(tot);
    for (int i = tid; i < VDIM / 4; i += 512) {
        float4 v = ((const float4*)srow)[i];
        v.x -= lse; v.y -= lse; v.z -= lse; v.w -= lse;
        ((float4*)x)[i] = v;
    }
}

// ---------------------------------------------------------------------------
// Tail: h_last and attentions (= ones).
// ---------------------------------------------------------------------------
__global__ void tail_kernel(float* __restrict__ out) {
    const int i = blockIdx.x * 256 + threadIdx.x;
    const size_t HOFF = (size_t)MDIM * VDIM;
    if (i < BDIM * HDIM) out[HOFF + i] = g_h[0][i];
    if (i < BDIM * TDIM) out[HOFF + BDIM * HDIM + i] = 1.0f;
}

// ---------------------------------------------------------------------------
extern "C" void kernel_launch(void* const* d_in, const int* in_sizes, int n_in,
                              void* d_out, int out_size) {
    const int*   lyr   = (const int*)d_in[0];
    const int*   iseq  = (const int*)d_in[1];
    const int*   tgt   = (const int*)d_in[2];
    const float* emb   = (const float*)d_in[3];
    // d_in[4..9]: Wa, ba, Ua, ub, Va, vb -> dead (softmax over length-1 axis)
    const float* tfidf_ = (const float*)d_in[10];
    const float* lyrW  = (const float*)d_in[11];
    const float* lyrb  = (const float*)d_in[12];
    const float* Wih   = (const float*)d_in[13];
    // d_in[14] Whh, 15 bih, 16 bhh
    const float* Whh   = (const float*)d_in[14];
    const float* bih   = (const float*)d_in[15];
    const float* bhh   = (const float*)d_in[16];
    const float* outW  = (const float*)d_in[17];
    const float* outb  = (const float*)d_in[18];
    float* out = (float*)d_out;

    cudaFuncSetAttribute(logsoftmax_kernel,
                         cudaFuncAttributeMaxDynamicSharedMemorySize,
                         LSM_SMEM + 1024);

    stok_kernel<<<(MDIM + 255) / 256, 256>>>(iseq, tgt);

    dim3 gi_grid(MDIM / GIM, GDIM / GIN);    // (32, 18)
    gi_kernel<<<gi_grid, 256>>>(emb, Wih);

    gru_kernel<<<NCTA_A, 512>>>(lyr, tfidf_, lyrW, lyrb, Whh, bih, bhh);

    convert_kernel<<<1024, 256>>>(outW);

    dim3 gg(MDIM / TM, VDIM / TN);           // (16, 250)
    gemm_kernel<<<gg, 256>>>(outb, out);

    logsoftmax_kernel<<<MDIM, 512, LSM_SMEM>>>(out);

    tail_kernel<<<(BDIM * TDIM + 255) / 256 + 12, 256>>>(out);
}

// round 8
// speedup vs baseline: 2.9826x; 1.0052x over previous
#include <cuda_runtime.h>
#include <cuda_bf16.h>
#include <cstdint>

// ---------------------------------------------------------------------------
// ConditionedAttnGRUDecoder  (H=768, V=32000, TF=1024, B=4, T=512)
//  * softmax over length-1 axis == 1 -> ctx == h_prev, attentions == ones,
//    Wa/ba/Ua/ub/Va/vb are dead inputs.
//  * log_softmax twice == once.
//  * gi = x@Wih^T precomputed for ALL steps (tokens known upfront).
//  * recurrent loop: only gh = h@Whh^T, with Whh in REGISTERS.
//  * output projection: ONE bf16 HMMA GEMM (portable mma.sync m16n8k16).
// ---------------------------------------------------------------------------

#define HDIM 768
#define BDIM 4
#define TDIM 512
#define TFDIM 1024
#define VDIM 32000
#define MDIM (BDIM * TDIM)       // 2048
#define GDIM (3 * HDIM)          // 2304

#define NCTA_A 96                // GRU CTAs (96 x 16 warps; 2 warps per j)

typedef unsigned long long ull;

// ----------------------------- device scratch ------------------------------
__device__ float g_h[2][BDIM * HDIM];                   // hidden double buffer
__device__ __align__(16) __nv_bfloat16 g_Hbf[(size_t)MDIM * HDIM];
__device__ __align__(16) __nv_bfloat16 g_Wbf[(size_t)VDIM * HDIM];
__device__ __align__(16) float g_gi[(size_t)MDIM * GDIM];   // precomputed x-gates
__device__ int g_stok[MDIM];                            // token per (t*4+b)
__device__ unsigned g_bar_count = 0;
__device__ unsigned g_bar_gen = 0;

// ----------------------------- helpers -------------------------------------
__device__ __forceinline__ ull fma2(ull a, ull b, ull c) {
    ull d;
    asm("fma.rn.f32x2 %0, %1, %2, %3;" : "=l"(d) : "l"(a), "l"(b), "l"(c));
    return d;
}
__device__ __forceinline__ ull pack2(float x, float y) {
    ull r;
    asm("mov.b64 %0, {%1, %2};" : "=l"(r) : "f"(x), "f"(y));
    return r;
}
__device__ __forceinline__ float2 unpack2(ull v) {
    float2 r;
    asm("mov.b64 {%0, %1}, %2;" : "=f"(r.x), "=f"(r.y) : "l"(v));
    return r;
}
__device__ __forceinline__ float wredsum(float v) {
#pragma unroll
    for (int o = 16; o; o >>= 1) v += __shfl_xor_sync(0xffffffffu, v, o);
    return v;
}
__device__ __forceinline__ float wredmax(float v) {
#pragma unroll
    for (int o = 16; o; o >>= 1) v = fmaxf(v, __shfl_xor_sync(0xffffffffu, v, o));
    return v;
}
__device__ __forceinline__ float sigmoidf_(float x) {
    return 1.0f / (1.0f + __expf(-x));
}
__device__ __forceinline__ uint32_t smem_u32(const void* p) {
    uint32_t a;
    asm("{ .reg .u64 t; cvta.to.shared.u64 t, %1; cvt.u32.u64 %0, t; }"
        : "=r"(a) : "l"(p));
    return a;
}

// grid-wide barrier (all NCTA_A CTAs resident)
__device__ __forceinline__ void grid_barrier() {
    __syncthreads();
    if (threadIdx.x == 0) {
        __threadfence();
        unsigned gen = *(volatile unsigned*)&g_bar_gen;
        unsigned t = atomicAdd(&g_bar_count, 1u);
        if (t == NCTA_A - 1) {
            g_bar_count = 0;
            __threadfence();
            atomicExch(&g_bar_gen, gen + 1u);
        } else {
            while (*(volatile unsigned*)&g_bar_gen == gen) { __nanosleep(32); }
        }
        __threadfence();
    }
    __syncthreads();
}

// ---------------------------------------------------------------------------
// stok: token fed at step t for batch b  ->  g_stok[t*4+b]
// ---------------------------------------------------------------------------
__global__ void stok_kernel(const int* __restrict__ iseq,
                            const int* __restrict__ tgt) {
    int idx = blockIdx.x * 256 + threadIdx.x;
    if (idx < MDIM) {
        int t = idx >> 2, b = idx & 3;
        g_stok[idx] = (t == 0) ? iseq[b * TDIM] : tgt[b * TDIM + t - 1];
    }
}

// ---------------------------------------------------------------------------
// gi GEMM (fp32): g_gi[m][n] = emb[stok[m]] . Wih[n]   (m=t*4+b, n=g*768+j)
// Tile 64x128x32, 256 threads, f32x2 FFMA (R3-proven structure + A gather).
// ---------------------------------------------------------------------------
#define GIM 64
#define GIN 128
#define GIK 32

__global__ void __launch_bounds__(256)
gi_kernel(const float* __restrict__ emb, const float* __restrict__ Wih) {
    __shared__ float sA[GIK][GIM];
    __shared__ float sW[GIK][GIN];
    __shared__ int stk[GIM];

    const int tid = threadIdx.x;
    const int m0 = blockIdx.x * GIM;
    const int n0 = blockIdx.y * GIN;
    const int tm = tid & 15;
    const int tn = tid >> 4;

    if (tid < GIM) stk[tid] = g_stok[m0 + tid];
    __syncthreads();

    ull c2[4][4];
#pragma unroll
    for (int i = 0; i < 4; ++i)
#pragma unroll
        for (int jj = 0; jj < 4; ++jj) c2[i][jj] = 0ULL;

    for (int kc = 0; kc < HDIM / GIK; ++kc) {
        const int kbase = kc * GIK;
#pragma unroll
        for (int q = 0; q < 2; ++q) {
            int idx = q * 256 + tid;
            int m = idx & 63;
            int k4 = (idx >> 6) * 4;
            float4 a = *(const float4*)(emb + (size_t)stk[m] * HDIM + kbase + k4);
            sA[k4 + 0][m] = a.x; sA[k4 + 1][m] = a.y;
            sA[k4 + 2][m] = a.z; sA[k4 + 3][m] = a.w;
        }
#pragma unroll
        for (int q = 0; q < 4; ++q) {
            int idx = q * 256 + tid;
            int n = idx & 127;
            int k4 = (idx >> 7) * 4;
            float4 w = *(const float4*)(Wih + (size_t)(n0 + n) * HDIM + kbase + k4);
            sW[k4 + 0][n] = w.x; sW[k4 + 1][n] = w.y;
            sW[k4 + 2][n] = w.z; sW[k4 + 3][n] = w.w;
        }
        __syncthreads();

#pragma unroll 8
        for (int kk = 0; kk < GIK; ++kk) {
            float4 a4 = *(const float4*)(&sA[kk][tm * 4]);
            ulonglong2 wA = *(const ulonglong2*)(&sW[kk][tn * 8]);
            ulonglong2 wB = *(const ulonglong2*)(&sW[kk][tn * 8 + 4]);
            ull a2[4];
            a2[0] = pack2(a4.x, a4.x);
            a2[1] = pack2(a4.y, a4.y);
            a2[2] = pack2(a4.z, a4.z);
            a2[3] = pack2(a4.w, a4.w);
#pragma unroll
            for (int i = 0; i < 4; ++i) {
                c2[i][0] = fma2(a2[i], wA.x, c2[i][0]);
                c2[i][1] = fma2(a2[i], wA.y, c2[i][1]);
                c2[i][2] = fma2(a2[i], wB.x, c2[i][2]);
                c2[i][3] = fma2(a2[i], wB.y, c2[i][3]);
            }
        }
        __syncthreads();
    }

#pragma unroll
    for (int i = 0; i < 4; ++i) {
        float* orow = g_gi + (size_t)(m0 + tm * 4 + i) * GDIM + n0 + tn * 8;
#pragma unroll
        for (int jj = 0; jj < 4; ++jj)
            *(float2*)(orow + jj * 2) = unpack2(c2[i][jj]);
    }
}

// ---------------------------------------------------------------------------
// GRU recurrence: 96 CTAs x 512 threads (16 warps). Warp w handles
// j = bx*8 + (w&7), k-half = (w>>3)*384. Whh rows live in REGISTERS.
// Per step: gh dots (regs x g_h), warp reduce, cross-half combine in smem,
// lanes 0-3 (b=lane) compute gates and write g_h + g_Hbf(bf16).
// ---------------------------------------------------------------------------
__global__ void __launch_bounds__(512, 1)
gru_kernel(const int* __restrict__ lyr, const float* __restrict__ tfidf_,
           const float* __restrict__ lyrW, const float* __restrict__ lyrb,
           const float* __restrict__ Whh, const float* __restrict__ bih,
           const float* __restrict__ bhh) {
    __shared__ float spart[16][12];

    const int tid = threadIdx.x;
    const int lane = tid & 31;
    const int w = tid >> 5;
    const int j = blockIdx.x * 8 + (w & 7);
    const int half = w >> 3;
    const int kb = half * 384 + lane * 4;

    // gate biases (used by lanes 0-3 of warps 0-7)
    const float bIRH = bih[j] + bhh[j];
    const float bIZH = bih[HDIM + j] + bhh[HDIM + j];
    const float bIN  = bih[2 * HDIM + j];
    const float bHN  = bhh[2 * HDIM + j];

    // Whh rows in registers: 3 gates x 3 k-chunks x 16B
    ulonglong2 whv[3][3];
#pragma unroll
    for (int g = 0; g < 3; ++g)
#pragma unroll
        for (int it = 0; it < 3; ++it)
            whv[g][it] = *(const ulonglong2*)(
                Whh + ((size_t)g * HDIM + j) * HDIM + kb + it * 128);

    // ---- h0[b][j] = dot(tfidf[lyr[b]], lyr_W[j]) + lyr_b[j]  (half==0) ----
    if (half == 0) {
        const float* wrow = lyrW + (size_t)j * TFDIM;
#pragma unroll
        for (int b = 0; b < BDIM; ++b) {
            const float* trow = tfidf_ + (size_t)lyr[b] * TFDIM;
            float acc = 0.0f;
#pragma unroll
            for (int it = 0; it < 8; ++it) {
                int k = it * 128 + lane * 4;
                float4 tv = *(const float4*)(trow + k);
                float4 wv = *(const float4*)(wrow + k);
                acc = fmaf(tv.x, wv.x, acc);
                acc = fmaf(tv.y, wv.y, acc);
                acc = fmaf(tv.z, wv.z, acc);
                acc = fmaf(tv.w, wv.w, acc);
            }
            acc = wredsum(acc);
            if (lane == 0) g_h[0][b * HDIM + j] = acc + lyrb[j];
        }
    }
    grid_barrier();

    for (int t = 0; t < TDIM; ++t) {
        const int rb = t & 1, wb = rb ^ 1;

        // prefetch this step's x-gates (independent of h)
        float gvR, gvZ, gvN;
        if (w < 8 && lane < 4) {
            const float* gp = g_gi + (size_t)(t * 4 + lane) * GDIM + j;
            gvR = gp[0];
            gvZ = gp[HDIM];
            gvN = gp[2 * HDIM];
        }

        // gh partial dots from register weights
        ull aR[4], aZ[4], aN[4];
#pragma unroll
        for (int b = 0; b < BDIM; ++b) { aR[b] = 0; aZ[b] = 0; aN[b] = 0; }
#pragma unroll
        for (int it = 0; it < 3; ++it) {
            const float* hb = g_h[rb] + kb + it * 128;
#pragma unroll
            for (int b = 0; b < BDIM; ++b) {
                ulonglong2 h = *(const ulonglong2*)(hb + b * HDIM);
                aR[b] = fma2(whv[0][it].x, h.x, aR[b]);
                aR[b] = fma2(whv[0][it].y, h.y, aR[b]);
                aZ[b] = fma2(whv[1][it].x, h.x, aZ[b]);
                aZ[b] = fma2(whv[1][it].y, h.y, aZ[b]);
                aN[b] = fma2(whv[2][it].x, h.x, aN[b]);
                aN[b] = fma2(whv[2][it].y, h.y, aN[b]);
            }
        }

        // intra-warp reduce 12 sums
        float sR[4], sZ[4], sN[4];
#pragma unroll
        for (int b = 0; b < BDIM; ++b) {
            float2 v;
            v = unpack2(aR[b]); sR[b] = wredsum(v.x + v.y);
            v = unpack2(aZ[b]); sZ[b] = wredsum(v.x + v.y);
            v = unpack2(aN[b]); sN[b] = wredsum(v.x + v.y);
        }
        if (lane == 0) {
#pragma unroll
            for (int b = 0; b < BDIM; ++b) {
                spart[w][b * 3 + 0] = sR[b];
                spart[w][b * 3 + 1] = sZ[b];
                spart[w][b * 3 + 2] = sN[b];
            }
        }
        __syncthreads();

        if (w < 8 && lane < 4) {
            const int b = lane;
            float ghr = spart[w][b * 3 + 0] + spart[w + 8][b * 3 + 0];
            float ghz = spart[w][b * 3 + 1] + spart[w + 8][b * 3 + 1];
            float ghn = spart[w][b * 3 + 2] + spart[w + 8][b * 3 + 2];
            float r = sigmoidf_(gvR + bIRH + ghr);
            float z = sigmoidf_(gvZ + bIZH + ghz);
            float n = tanhf(gvN + bIN + r * (ghn + bHN));
            float hp = g_h[rb][b * HDIM + j];
            float hn_ = (1.0f - z) * n + z * hp;
            g_h[wb][b * HDIM + j] = hn_;
            g_Hbf[(size_t)(b * TDIM + t) * HDIM + j] = __float2bfloat16(hn_);
        }
        grid_barrier();
    }
}

// ---------------------------------------------------------------------------
// fp32 -> bf16 convert of out_W only (H states already written as bf16).
// ---------------------------------------------------------------------------
__global__ void __launch_bounds__(256)
convert_kernel(const float* __restrict__ outW) {
    const size_t i0 = (size_t)blockIdx.x * blockDim.x + threadIdx.x;
    const size_t stride = (size_t)gridDim.x * blockDim.x;
    const size_t NW4 = (size_t)VDIM * HDIM / 4;
    for (size_t k = i0; k < NW4; k += stride) {
        float4 v = ((const float4*)outW)[k];
        ((__nv_bfloat162*)g_Wbf)[k * 2]     = __floats2bfloat162_rn(v.x, v.y);
        ((__nv_bfloat162*)g_Wbf)[k * 2 + 1] = __floats2bfloat162_rn(v.z, v.w);
    }
}

// ---------------------------------------------------------------------------
// Phase B: HMMA GEMM  C[2048,32000] = Hbf @ Wbf.T + out_b  (unchanged, R5 pass)
// ---------------------------------------------------------------------------
#define TM 128
#define TN 128
#define TK 32
#define NCHUNK (HDIM / TK)       // 24
#define SPAD 40                  // bf16 per smem row (80B stride)

__device__ __forceinline__ void ldmx4(uint32_t* r, uint32_t addr) {
    asm volatile("ldmatrix.sync.aligned.m8n8.x4.shared.b16 {%0,%1,%2,%3}, [%4];"
                 : "=r"(r[0]), "=r"(r[1]), "=r"(r[2]), "=r"(r[3]) : "r"(addr));
}
__device__ __forceinline__ void hmma(float* d, const uint32_t* a,
                                     const uint32_t* b) {
    asm volatile(
        "mma.sync.aligned.m16n8k16.row.col.f32.bf16.bf16.f32 "
        "{%0,%1,%2,%3}, {%4,%5,%6,%7}, {%8,%9}, {%0,%1,%2,%3};"
        : "+f"(d[0]), "+f"(d[1]), "+f"(d[2]), "+f"(d[3])
        : "r"(a[0]), "r"(a[1]), "r"(a[2]), "r"(a[3]), "r"(b[0]), "r"(b[1]));
}

__global__ void __launch_bounds__(256, 2)
gemm_kernel(const float* __restrict__ outb, float* __restrict__ out) {
    __shared__ __nv_bfloat16 sA[2][TM][SPAD];
    __shared__ __nv_bfloat16 sB[2][TN][SPAD];
    __shared__ float sbias[TN];

    const int tid = threadIdx.x;
    const int lane = tid & 31;
    const int wid = tid >> 5;
    const int wm = wid & 3;
    const int wn = wid >> 2;
    const size_t m0 = (size_t)blockIdx.x * TM;
    const size_t n0 = (size_t)blockIdx.y * TN;

    for (int i = tid; i < TN; i += 256) sbias[i] = outb[n0 + i];

    const int grow = tid >> 2;
    const int gseg = tid & 3;

    const __nv_bfloat16* gA = g_Hbf + (m0 + grow) * HDIM + gseg * 8;
    const __nv_bfloat16* gB = g_Wbf + (n0 + grow) * HDIM + gseg * 8;

    {
#pragma unroll
        for (int q = 0; q < 2; ++q) {
            uint4 a = *(const uint4*)(gA + q * 64 * HDIM);
            uint4 b = *(const uint4*)(gB + q * 64 * HDIM);
            *(uint4*)(&sA[0][grow + q * 64][gseg * 8]) = a;
            *(uint4*)(&sB[0][grow + q * 64][gseg * 8]) = b;
        }
    }
    __syncthreads();

    float acc[2][8][4];
#pragma unroll
    for (int am = 0; am < 2; ++am)
#pragma unroll
        for (int bn = 0; bn < 8; ++bn)
#pragma unroll
            for (int q = 0; q < 4; ++q) acc[am][bn][q] = 0.0f;

    const int a_r = lane & 15, a_c = (lane >> 4) * 8;
    const int b_g = lane >> 3;
    const int b_r = ((b_g >> 1) << 3) + (lane & 7);
    const int b_c = (b_g & 1) * 8;

    for (int c = 0; c < NCHUNK; ++c) {
        const int p = c & 1;
        const bool more = (c + 1) < NCHUNK;
        uint4 pa0, pa1, pb0, pb1;
        if (more) {
            const __nv_bfloat16* sa = gA + (size_t)(c + 1) * TK;
            const __nv_bfloat16* sb2 = gB + (size_t)(c + 1) * TK;
            pa0 = *(const uint4*)(sa);
            pa1 = *(const uint4*)(sa + 64 * HDIM);
            pb0 = *(const uint4*)(sb2);
            pb1 = *(const uint4*)(sb2 + 64 * HDIM);
        }

#pragma unroll
        for (int ks = 0; ks < 2; ++ks) {
            const int k8 = ks * 16;
            uint32_t afr[2][4], bfr[4][4];
#pragma unroll
            for (int am = 0; am < 2; ++am)
                ldmx4(afr[am],
                      smem_u32(&sA[p][wm * 32 + am * 16 + a_r][k8 + a_c]));
#pragma unroll
            for (int bg = 0; bg < 4; ++bg)
                ldmx4(bfr[bg],
                      smem_u32(&sB[p][wn * 64 + bg * 16 + b_r][k8 + b_c]));
#pragma unroll
            for (int am = 0; am < 2; ++am)
#pragma unroll
                for (int bn = 0; bn < 8; ++bn)
                    hmma(acc[am][bn], afr[am], &bfr[bn >> 1][(bn & 1) * 2]);
        }

        if (more) {
            *(uint4*)(&sA[p ^ 1][grow][gseg * 8]) = pa0;
            *(uint4*)(&sA[p ^ 1][grow + 64][gseg * 8]) = pa1;
            *(uint4*)(&sB[p ^ 1][grow][gseg * 8]) = pb0;
            *(uint4*)(&sB[p ^ 1][grow + 64][gseg * 8]) = pb1;
        }
        __syncthreads();
    }

#pragma unroll
    for (int am = 0; am < 2; ++am) {
#pragma unroll
        for (int half = 0; half < 2; ++half) {
            const size_t row = m0 + wm * 32 + am * 16 + half * 8 + (lane >> 2);
            float* orow = out + row * VDIM + n0 + wn * 64 + (lane & 3) * 2;
#pragma unroll
            for (int bn = 0; bn < 8; ++bn) {
                const int colL = wn * 64 + bn * 8 + (lane & 3) * 2;
                float2 v;
                v.x = acc[am][bn][half * 2 + 0] + sbias[colL];
                v.y = acc[am][bn][half * 2 + 1] + sbias[colL + 1];
                *(float2*)(orow + bn * 8) = v;
            }
        }
    }
}

// ---------------------------------------------------------------------------
// Row log_softmax, row cached in 125 KB smem: 1 DRAM read + 1 DRAM write.
// ---------------------------------------------------------------------------
#define LSM_SMEM (VDIM * 4)

__global__ void __launch_bounds__(512)
logsoftmax_kernel(float* __restrict__ out) {
    extern __shared__ float srow[];
    __shared__ float red[16];
    const int tid = threadIdx.x;
    const int lane = tid & 31;
    const int wid = tid >> 5;
    float* x = out + (size_t)blockIdx.x * VDIM;

    float m = -3.4e38f;
    for (int i = tid; i < VDIM / 4; i += 512) {
        float4 v = ((const float4*)x)[i];
        ((float4*)srow)[i] = v;
        m = fmaxf(fmaxf(m, fmaxf(v.x, v.y)), fmaxf(v.z, v.w));
    }
    m = wredmax(m);
    if (lane == 0) red[wid] = m;
    __syncthreads();
#pragma unroll
    for (int q = 0; q < 16; ++q) m = fmaxf(m, red[q]);
    __syncthreads();

    float s = 0.0f;
    for (int i = tid; i < VDIM / 4; i += 512) {
        float4 v = ((const float4*)srow)[i];
        s += __expf(v.x - m) + __expf(v.y - m) +
             __expf(v.z - m) + __expf(v.w - m);
    }
    s = wredsum(s);
    if (lane == 0) red[wid] = s;
    __syncthreads();
    float tot = 0.0f;
#pragma unroll
    for (int q = 0; q < 16; ++q) tot += red[q];

    const float lse = m + logf(tot);
    for (int i = tid; i < VDIM / 4; i += 512) {
        float4 v = ((const float4*)srow)[i];
        v.x -= lse; v.y -= lse; v.z -= lse; v.w -= lse;
        ((float4*)x)[i] = v;
    }
}

// ---------------------------------------------------------------------------
// Tail: h_last and attentions (= ones).
// ---------------------------------------------------------------------------
__global__ void tail_kernel(float* __restrict__ out) {
    const int i = blockIdx.x * 256 + threadIdx.x;
    const size_t HOFF = (size_t)MDIM * VDIM;
    if (i < BDIM * HDIM) out[HOFF + i] = g_h[0][i];
    if (i < BDIM * TDIM) out[HOFF + BDIM * HDIM + i] = 1.0f;
}

// ---------------------------------------------------------------------------
extern "C" void kernel_launch(void* const* d_in, const int* in_sizes, int n_in,
                              void* d_out, int out_size) {
    const int*   lyr   = (const int*)d_in[0];
    const int*   iseq  = (const int*)d_in[1];
    const int*   tgt   = (const int*)d_in[2];
    const float* emb   = (const float*)d_in[3];
    // d_in[4..9]: Wa, ba, Ua, ub, Va, vb -> dead (softmax over length-1 axis)
    const float* tfidf_ = (const float*)d_in[10];
    const float* lyrW  = (const float*)d_in[11];
    const float* lyrb  = (const float*)d_in[12];
    const float* Wih   = (const float*)d_in[13];
    // d_in[14] Whh, 15 bih, 16 bhh
    const float* Whh   = (const float*)d_in[14];
    const float* bih   = (const float*)d_in[15];
    const float* bhh   = (const float*)d_in[16];
    const float* outW  = (const float*)d_in[17];
    const float* outb  = (const float*)d_in[18];
    float* out = (float*)d_out;

    cudaFuncSetAttribute(logsoftmax_kernel,
                         cudaFuncAttributeMaxDynamicSharedMemorySize,
                         LSM_SMEM + 1024);

    stok_kernel<<<(MDIM + 255) / 256, 256>>>(iseq, tgt);

    dim3 gi_grid(MDIM / GIM, GDIM / GIN);    // (32, 18)
    gi_kernel<<<gi_grid, 256>>>(emb, Wih);

    gru_kernel<<<NCTA_A, 512>>>(lyr, tfidf_, lyrW, lyrb, Whh, bih, bhh);

    convert_kernel<<<1024, 256>>>(outW);

    dim3 gg(MDIM / TM, VDIM / TN);           // (16, 250)
    gemm_kernel<<<gg, 256>>>(outb, out);

    logsoftmax_kernel<<<MDIM, 512, LSM_SMEM>>>(out);

    tail_kernel<<<(BDIM * TDIM + 255) / 256 + 12, 256>>>(out);
}